// round 12
// baseline (speedup 1.0000x reference)
#include <cuda_runtime.h>
#include <cuda_bf16.h>
#include <math.h>
#include <stdint.h>

#define Bn 1024
#define In 512
#define Hn 2048
#define On 512
#define En 8

// ---------------- scratch (device globals; zero-init, 16B aligned; ~80MB proven budget) ----------------
__device__ __align__(16) int   g_counts[En];
__device__ __align__(16) int   g_tok[En * Bn];
__device__ __align__(16) int   g_pos[Bn * 2];
__device__ __align__(16) float g_wk[Bn * 2];
__device__ __align__(16) __nv_bfloat16 g_hhi[En * Bn * Hn];   // 32 MB
__device__ __align__(16) __nv_bfloat16 g_hlo[En * Bn * Hn];   // 32 MB
__device__ __align__(16) float g_y[En * Bn * On];             // 16 MB

// ---------------- mma / ldmatrix / cp.async helpers ----------------
__device__ __forceinline__ void mma_bf16(float* c, const uint32_t* a, const uint32_t* b) {
    asm volatile(
        "mma.sync.aligned.m16n8k16.row.col.f32.bf16.bf16.f32 "
        "{%0,%1,%2,%3}, {%4,%5,%6,%7}, {%8,%9}, {%0,%1,%2,%3};"
        : "+f"(c[0]), "+f"(c[1]), "+f"(c[2]), "+f"(c[3])
        : "r"(a[0]), "r"(a[1]), "r"(a[2]), "r"(a[3]), "r"(b[0]), "r"(b[1]));
}
__device__ __forceinline__ void ldsm_x4(uint32_t& r0, uint32_t& r1, uint32_t& r2, uint32_t& r3,
                                        uint32_t addr) {
    asm volatile("ldmatrix.sync.aligned.m8n8.x4.shared.b16 {%0,%1,%2,%3}, [%4];"
        : "=r"(r0), "=r"(r1), "=r"(r2), "=r"(r3) : "r"(addr));
}
#define CP16(dst, src) asm volatile("cp.async.cg.shared.global [%0], [%1], 16;" :: "r"(dst), "l"(src))
#define CPCOMMIT()     asm volatile("cp.async.commit_group;" ::: "memory")
#define CPWAIT1()      asm volatile("cp.async.wait_group 1;" ::: "memory")
#define CPWAIT0()      asm volatile("cp.async.wait_group 0;" ::: "memory")

__device__ __forceinline__ void split_bf16(float v, __nv_bfloat16& h, __nv_bfloat16& l) {
    h = __float2bfloat16(v);
    l = __float2bfloat16(v - __bfloat162float(h));
}
__device__ __forceinline__ uint32_t pack2(__nv_bfloat16 a, __nv_bfloat16 b) {
    return ((uint32_t)__bfloat16_as_ushort(b) << 16) | __bfloat16_as_ushort(a);
}

// ---------------- pad-free swizzled smem plane (proven R9-R11) ----------------
// plane: rows x 32 k bf16 = 64 B/row = 4 chunks of 16 B.
// phys(r, chunk c) = r*64 + ((c ^ ((r>>1)&3)) * 16)
#define PLANE_P  4096                 // 64 rows (all planes now 64 rows)
#define SWZ_R(r) (((r) >> 1) & 3)
#define BUF_B    (4 * PLANE_P)        // Ahi|Alo|Bhi|Blo = 16384
#define GSMEM    (3 * BUF_B)          // 49152: triple buffer (proven size)

// ---------------- kernel 0: zero counters ----------------
__global__ void zero_counts_kernel() {
    if (threadIdx.x < En) g_counts[threadIdx.x] = 0;
}

// ---------------- kernel 1: gating (proven) ----------------
__global__ void gate_kernel(const float* __restrict__ x,
                            const float* __restrict__ Wg,
                            const float* __restrict__ bg) {
    int warp = threadIdx.x >> 5, lane = threadIdx.x & 31;
    int b = blockIdx.x * 8 + warp;
    const float* xr = x + (size_t)b * In;

    float acc[En];
#pragma unroll
    for (int e = 0; e < En; e++) acc[e] = 0.f;
    for (int i = lane; i < In; i += 32) {
        float xv = xr[i];
        const float4* w4 = reinterpret_cast<const float4*>(Wg + (size_t)i * En);
        float4 w0 = w4[0], w1 = w4[1];
        acc[0] += xv * w0.x; acc[1] += xv * w0.y;
        acc[2] += xv * w0.z; acc[3] += xv * w0.w;
        acc[4] += xv * w1.x; acc[5] += xv * w1.y;
        acc[6] += xv * w1.z; acc[7] += xv * w1.w;
    }
#pragma unroll
    for (int e = 0; e < En; e++) {
#pragma unroll
        for (int off = 16; off; off >>= 1)
            acc[e] += __shfl_xor_sync(0xffffffffu, acc[e], off);
    }
    if (lane == 0) {
        float lg[En]; float m = -1e30f;
#pragma unroll
        for (int e = 0; e < En; e++) { lg[e] = acc[e] + bg[e]; m = fmaxf(m, lg[e]); }
        float p[En]; float s = 0.f;
#pragma unroll
        for (int e = 0; e < En; e++) { p[e] = expf(lg[e] - m); s += p[e]; }
#pragma unroll
        for (int e = 0; e < En; e++) p[e] /= s;
        int i0 = 0;
#pragma unroll
        for (int e = 1; e < En; e++) if (p[e] > p[i0]) i0 = e;
        int i1 = (i0 == 0) ? 1 : 0;
#pragma unroll
        for (int e = 0; e < En; e++) if (e != i0 && p[e] > p[i1]) i1 = e;
        float sum2 = p[i0] + p[i1];
        float w0 = p[i0] / sum2, w1 = p[i1] / sum2;
        int s0 = atomicAdd(&g_counts[i0], 1);
        g_tok[i0 * Bn + s0] = b;
        g_pos[b * 2 + 0] = i0 * Bn + s0;
        g_wk[b * 2 + 0] = w0;
        int s1 = atomicAdd(&g_counts[i1], 1);
        g_tok[i1 * Bn + s1] = b;
        g_pos[b * 2 + 1] = i1 * Bn + s1;
        g_wk[b * 2 + 1] = w1;
    }
}

// ---------------- compute via ldmatrix.x4 (proven R10/R11; MT=1, 64x64 tile) ----------------
__device__ __forceinline__ void compute_tile(uint32_t sbuf, int lane, int warp_m, int warp_n,
                                             float acc[4][4]) {
    uint32_t Ahi = sbuf, Alo = sbuf + PLANE_P;
    uint32_t Bhi = sbuf + 2 * PLANE_P, Blo = Bhi + PLANE_P;
    int rsel = lane & 7, grp = lane >> 3;
#pragma unroll
    for (int ks = 0; ks < 2; ks++) {
        uint32_t bh[4][2], bl[4][2];
#pragma unroll
        for (int p = 0; p < 2; p++) {
            int nt = 2 * p + (grp >> 1);
            int n = warp_n * 32 + nt * 8 + rsel;
            int cB = 2 * ks + (grp & 1);
            uint32_t off = (uint32_t)n * 64 + (uint32_t)((cB ^ SWZ_R(n)) << 4);
            ldsm_x4(bh[2 * p][0], bh[2 * p][1], bh[2 * p + 1][0], bh[2 * p + 1][1], Bhi + off);
            ldsm_x4(bl[2 * p][0], bl[2 * p][1], bl[2 * p + 1][0], bl[2 * p + 1][1], Blo + off);
        }
        {
            int r = warp_m * 16 + ((grp & 1) << 3) + rsel;
            int cA = 2 * ks + (grp >> 1);
            uint32_t off = (uint32_t)r * 64 + (uint32_t)((cA ^ SWZ_R(r)) << 4);
            uint32_t ah[4], al[4];
            ldsm_x4(ah[0], ah[1], ah[2], ah[3], Ahi + off);
            ldsm_x4(al[0], al[1], al[2], al[3], Alo + off);
#pragma unroll
            for (int nt = 0; nt < 4; nt++) {
                mma_bf16(acc[nt], ah, bh[nt]);
                mma_bf16(acc[nt], ah, bl[nt]);
                mma_bf16(acc[nt], al, bh[nt]);
            }
        }
    }
}

// ======================= GEMM1: gathered x @ W1[e], +b1, ReLU -> g_hhi/g_hlo =======================
// M=64, N=64, 3-stage pipeline, split-load for A (gathered) and B.
__global__ void __launch_bounds__(256, 2) gemm1_mma(const float* __restrict__ x,
                                                    const float* __restrict__ W1,
                                                    const float* __restrict__ b1) {
    extern __shared__ char smem[];
    uint32_t sbase = (uint32_t)__cvta_generic_to_shared(smem);
    int tid = threadIdx.x, wid = tid >> 5, lane = tid & 31;
    int warp_m = wid & 3, warp_n = wid >> 2;

    int e = blockIdx.z;
    int count = g_counts[e];
    int m0 = blockIdx.y * 64;
    if (m0 >= count) return;
    int n0 = blockIdx.x * 64;

    const float* W1e = W1 + (size_t)e * In * Hn;

    float acc[4][4];
#pragma unroll
    for (int j = 0; j < 4; j++)
#pragma unroll
        for (int k = 0; k < 4; k++) acc[j][k] = 0.f;

    // A: row = tid>>2 (0..63), chunk = tid&3 (8 floats). Token fixed per thread.
    int arow = tid >> 2, ach = tid & 3;
    int agr = m0 + arow;
    int tok = g_tok[e * Bn + (agr < count ? agr : count - 1)];
    const float* Asrc = x + (size_t)tok * In + ach * 8;
    uint32_t adst = (uint32_t)arow * 64 + (uint32_t)((ach ^ SWZ_R(arow)) * 16);
    // B: n = tid&63, k-group = tid>>6 (8 strided rows)
    int bn = tid & 63, bkg = tid >> 6;
    uint32_t bdst = (uint32_t)bn * 64 + (uint32_t)((bkg ^ SWZ_R(bn)) * 16);

    float fA[8], fB[8];

    auto ld = [&](int kt) {
        float4 v0 = *reinterpret_cast<const float4*>(Asrc + kt);
        float4 v1 = *reinterpret_cast<const float4*>(Asrc + kt + 4);
        fA[0] = v0.x; fA[1] = v0.y; fA[2] = v0.z; fA[3] = v0.w;
        fA[4] = v1.x; fA[5] = v1.y; fA[6] = v1.z; fA[7] = v1.w;
        const float* src = W1e + (size_t)(kt + bkg * 8) * Hn + n0 + bn;
#pragma unroll
        for (int j = 0; j < 8; j++) fB[j] = src[(size_t)j * Hn];
    };
    auto st = [&](int b) {
        char* base = smem + b * BUF_B;
        uint32_t hi[4], lo[4];
#pragma unroll
        for (int j = 0; j < 4; j++) {
            __nv_bfloat16 h0, l0, h1, l1;
            split_bf16(fA[2 * j], h0, l0);
            split_bf16(fA[2 * j + 1], h1, l1);
            hi[j] = pack2(h0, h1); lo[j] = pack2(l0, l1);
        }
        *reinterpret_cast<uint4*>(base + adst)           = make_uint4(hi[0], hi[1], hi[2], hi[3]);
        *reinterpret_cast<uint4*>(base + PLANE_P + adst) = make_uint4(lo[0], lo[1], lo[2], lo[3]);
#pragma unroll
        for (int j = 0; j < 4; j++) {
            __nv_bfloat16 h0, l0, h1, l1;
            split_bf16(fB[2 * j], h0, l0);
            split_bf16(fB[2 * j + 1], h1, l1);
            hi[j] = pack2(h0, h1); lo[j] = pack2(l0, l1);
        }
        *reinterpret_cast<uint4*>(base + 2 * PLANE_P + bdst) = make_uint4(hi[0], hi[1], hi[2], hi[3]);
        *reinterpret_cast<uint4*>(base + 3 * PLANE_P + bdst) = make_uint4(lo[0], lo[1], lo[2], lo[3]);
    };

    const int NC = In / 32;    // 16
    ld(0);  st(0);
    ld(32); st(1);
    __syncthreads();
    for (int c = 0; c < NC; c++) {
        bool pre = (c + 2 < NC);
        if (pre) ld((c + 2) * 32);            // LDGs in flight during compute
        compute_tile(sbase + (uint32_t)((c % 3) * BUF_B), lane, warp_m, warp_n, acc);
        if (pre) st((c + 2) % 3);             // convert + STS after compute
        __syncthreads();
    }

    // epilogue: +bias, ReLU, split -> g_hhi/g_hlo
#pragma unroll
    for (int nt = 0; nt < 4; nt++) {
        int ncol_l = warp_n * 32 + nt * 8 + (lane & 3) * 2;
        float bb0 = b1[e * Hn + n0 + ncol_l];
        float bb1 = b1[e * Hn + n0 + ncol_l + 1];
#pragma unroll
        for (int h = 0; h < 2; h++) {
            int grow = m0 + warp_m * 16 + (lane >> 2) + h * 8;
            float v0 = fmaxf(acc[nt][h * 2 + 0] + bb0, 0.f);
            float v1 = fmaxf(acc[nt][h * 2 + 1] + bb1, 0.f);
            __nv_bfloat16 h0, h1, l0, l1;
            split_bf16(v0, h0, l0); split_bf16(v1, h1, l1);
            size_t off = (size_t)(e * Bn + grow) * Hn + n0 + ncol_l;
            *reinterpret_cast<uint32_t*>(g_hhi + off) = pack2(h0, h1);
            *reinterpret_cast<uint32_t*>(g_hlo + off) = pack2(l0, l1);
        }
    }
}

// ======================= GEMM2 (byte-identical to R11, proven): 3-stage, cp.async A =======================
__global__ void __launch_bounds__(256, 2) gemm2_mma(const float* __restrict__ W2) {
    extern __shared__ char smem[];
    uint32_t sbase = (uint32_t)__cvta_generic_to_shared(smem);
    int tid = threadIdx.x, wid = tid >> 5, lane = tid & 31;
    int warp_m = wid & 3, warp_n = wid >> 2;

    int e = blockIdx.z;
    int count = g_counts[e];
    int m0 = blockIdx.y * 64;
    if (m0 >= count) return;
    int n0 = blockIdx.x * 64;

    const __nv_bfloat16* Ahg = g_hhi + (size_t)(e * Bn + m0) * Hn;
    const __nv_bfloat16* Alg = g_hlo + (size_t)(e * Bn + m0) * Hn;
    const float* W2e = W2 + (size_t)e * Hn * On;

    float acc[4][4];
#pragma unroll
    for (int j = 0; j < 4; j++)
#pragma unroll
        for (int k = 0; k < 4; k++) acc[j][k] = 0.f;

    int arow = tid >> 2, ach = tid & 3;
    uint32_t adst = (uint32_t)arow * 64 + (uint32_t)((ach ^ SWZ_R(arow)) * 16);
    int bn = tid & 63, bkg = tid >> 6;
    uint32_t bdst = (uint32_t)bn * 64 + (uint32_t)((bkg ^ SWZ_R(bn)) * 16);

    float fB[8];

    auto aload = [&](int b, int kt) {
        size_t src = (size_t)arow * Hn + kt + ach * 8;
        uint32_t d = sbase + (uint32_t)(b * BUF_B) + adst;
        CP16(d, Ahg + src);
        CP16(d + PLANE_P, Alg + src);
    };
    auto bload = [&](int kt) {
        const float* src = W2e + (size_t)(kt + bkg * 8) * On + n0 + bn;
#pragma unroll
        for (int j = 0; j < 8; j++) fB[j] = src[(size_t)j * On];
    };
    auto bstore = [&](int b) {
        uint32_t hi[4], lo[4];
#pragma unroll
        for (int j = 0; j < 4; j++) {
            __nv_bfloat16 h0, l0, h1, l1;
            split_bf16(fB[2 * j], h0, l0);
            split_bf16(fB[2 * j + 1], h1, l1);
            hi[j] = pack2(h0, h1);
            lo[j] = pack2(l0, l1);
        }
        char* base = smem + b * BUF_B + 2 * PLANE_P;
        *reinterpret_cast<uint4*>(base + bdst)           = make_uint4(hi[0], hi[1], hi[2], hi[3]);
        *reinterpret_cast<uint4*>(base + PLANE_P + bdst) = make_uint4(lo[0], lo[1], lo[2], lo[3]);
    };

    const int NC = Hn / 32;    // 64

    bload(0);  aload(0, 0);  CPCOMMIT(); bstore(0);
    bload(32); aload(1, 32); CPCOMMIT(); bstore(1);

    for (int c = 0; c < NC; c++) {
        if (c + 1 < NC) { CPWAIT1(); } else { CPWAIT0(); }
        __syncthreads();
        bool pre = (c + 2 < NC);
        if (pre) {
            int kt2 = (c + 2) * 32;
            bload(kt2);
            aload((c + 2) % 3, kt2);
            CPCOMMIT();
        }
        compute_tile(sbase + (uint32_t)((c % 3) * BUF_B), lane, warp_m, warp_n, acc);
        if (pre) bstore((c + 2) % 3);
    }

#pragma unroll
    for (int nt = 0; nt < 4; nt++) {
        int ncol_l = warp_n * 32 + nt * 8 + (lane & 3) * 2;
#pragma unroll
        for (int h = 0; h < 2; h++) {
            int grow = m0 + warp_m * 16 + (lane >> 2) + h * 8;
            float2 v = make_float2(acc[nt][h * 2 + 0], acc[nt][h * 2 + 1]);
            *reinterpret_cast<float2*>(g_y + (size_t)(e * Bn + grow) * On + n0 + ncol_l) = v;
        }
    }
}

// ---------------- combine (+ b2) — proven ----------------
__global__ void combine_kernel(const float* __restrict__ b2, float* __restrict__ out) {
    int idx = blockIdx.x * 256 + threadIdx.x;
    int b = idx >> 7;
    int o = (idx & 127) * 4;
    int p0 = g_pos[b * 2 + 0], p1 = g_pos[b * 2 + 1];
    float w0 = g_wk[b * 2 + 0], w1 = g_wk[b * 2 + 1];
    int e0 = p0 >> 10, e1 = p1 >> 10;
    float4 y0 = *reinterpret_cast<const float4*>(g_y + (size_t)p0 * On + o);
    float4 y1 = *reinterpret_cast<const float4*>(g_y + (size_t)p1 * On + o);
    float4 c0 = *reinterpret_cast<const float4*>(b2 + (size_t)e0 * On + o);
    float4 c1 = *reinterpret_cast<const float4*>(b2 + (size_t)e1 * On + o);
    float4 r;
    r.x = w0 * (y0.x + c0.x) + w1 * (y1.x + c1.x);
    r.y = w0 * (y0.y + c0.y) + w1 * (y1.y + c1.y);
    r.z = w0 * (y0.z + c0.z) + w1 * (y1.z + c1.z);
    r.w = w0 * (y0.w + c0.w) + w1 * (y1.w + c1.w);
    *reinterpret_cast<float4*>(out + (size_t)b * On + o) = r;
}

// ---------------- launch ----------------
extern "C" void kernel_launch(void* const* d_in, const int* in_sizes, int n_in,
                              void* d_out, int out_size) {
    const float* x  = (const float*)d_in[0];
    const float* Wg = (const float*)d_in[1];
    const float* bg = (const float*)d_in[2];
    const float* W1 = (const float*)d_in[3];
    const float* b1 = (const float*)d_in[4];
    const float* W2 = (const float*)d_in[5];
    const float* b2 = (const float*)d_in[6];
    float* out = (float*)d_out;

    zero_counts_kernel<<<1, 32>>>();
    gate_kernel<<<Bn / 8, 256>>>(x, Wg, bg);
    gemm1_mma<<<dim3(Hn / 64, Bn / 64, En), 256, GSMEM>>>(x, W1, b1);
    gemm2_mma<<<dim3(On / 64, Bn / 64, En), 256, GSMEM>>>(W2);
    combine_kernel<<<(Bn * On / 4) / 256, 256>>>(b2, out);
}

// round 13
// speedup vs baseline: 1.0708x; 1.0708x over previous
#include <cuda_runtime.h>
#include <cuda_bf16.h>
#include <math.h>
#include <stdint.h>

#define Bn 1024
#define In 512
#define Hn 2048
#define On 512
#define En 8

// ---------------- scratch (device globals; zero-init, 16B aligned; ~96MB) ----------------
__device__ __align__(16) int   g_counts[En];
__device__ __align__(16) int   g_tok[En * Bn];
__device__ __align__(16) int   g_pos[Bn * 2];
__device__ __align__(16) float g_wk[Bn * 2];
__device__ __align__(16) __nv_bfloat16 g_hhi[En * Bn * Hn];   // 32 MB
__device__ __align__(16) __nv_bfloat16 g_hlo[En * Bn * Hn];   // 32 MB
__device__ __align__(16) float g_y[En * Bn * On];             // 16 MB (K-half 0)
__device__ __align__(16) float g_y2[En * Bn * On];            // 16 MB (K-half 1)

// ---------------- mma / ldmatrix / cp.async helpers ----------------
__device__ __forceinline__ void mma_bf16(float* c, const uint32_t* a, const uint32_t* b) {
    asm volatile(
        "mma.sync.aligned.m16n8k16.row.col.f32.bf16.bf16.f32 "
        "{%0,%1,%2,%3}, {%4,%5,%6,%7}, {%8,%9}, {%0,%1,%2,%3};"
        : "+f"(c[0]), "+f"(c[1]), "+f"(c[2]), "+f"(c[3])
        : "r"(a[0]), "r"(a[1]), "r"(a[2]), "r"(a[3]), "r"(b[0]), "r"(b[1]));
}
__device__ __forceinline__ void ldsm_x4(uint32_t& r0, uint32_t& r1, uint32_t& r2, uint32_t& r3,
                                        uint32_t addr) {
    asm volatile("ldmatrix.sync.aligned.m8n8.x4.shared.b16 {%0,%1,%2,%3}, [%4];"
        : "=r"(r0), "=r"(r1), "=r"(r2), "=r"(r3) : "r"(addr));
}
#define CP16(dst, src) asm volatile("cp.async.cg.shared.global [%0], [%1], 16;" :: "r"(dst), "l"(src))
#define CPCOMMIT()     asm volatile("cp.async.commit_group;" ::: "memory")
#define CPWAIT1()      asm volatile("cp.async.wait_group 1;" ::: "memory")
#define CPWAIT0()      asm volatile("cp.async.wait_group 0;" ::: "memory")

__device__ __forceinline__ void split_bf16(float v, __nv_bfloat16& h, __nv_bfloat16& l) {
    h = __float2bfloat16(v);
    l = __float2bfloat16(v - __bfloat162float(h));
}
__device__ __forceinline__ uint32_t pack2(__nv_bfloat16 a, __nv_bfloat16 b) {
    return ((uint32_t)__bfloat16_as_ushort(b) << 16) | __bfloat16_as_ushort(a);
}

// ---------------- pad-free swizzled smem planes (proven R9-R11) ----------------
// plane: rows x 32 k bf16 = 64 B/row = 4 chunks of 16 B.
// phys(r, chunk c) = r*64 + ((c ^ ((r>>1)&3)) * 16)
#define PLANE_Bp 4096                 // 64 rows
#define SWZ_R(r) (((r) >> 1) & 3)

#define PLANE_A1 8192                 // gemm1 A: 128 rows
#define BUF1_B   (2 * PLANE_A1 + 2 * PLANE_Bp)   // 24576
#define GSMEM1   (2 * BUF1_B)                    // 49152 (proven)

#define PLANE_A2 4096                 // gemm2 A: 64 rows
#define BUF2_B   (2 * PLANE_A2 + 2 * PLANE_Bp)   // 16384
#define GSMEM2   (3 * BUF2_B)                    // 49152 triple buffer (proven)

// ---------------- kernel 0: zero counters ----------------
__global__ void zero_counts_kernel() {
    if (threadIdx.x < En) g_counts[threadIdx.x] = 0;
}

// ---------------- kernel 1: gating (proven) ----------------
__global__ void gate_kernel(const float* __restrict__ x,
                            const float* __restrict__ Wg,
                            const float* __restrict__ bg) {
    int warp = threadIdx.x >> 5, lane = threadIdx.x & 31;
    int b = blockIdx.x * 8 + warp;
    const float* xr = x + (size_t)b * In;

    float acc[En];
#pragma unroll
    for (int e = 0; e < En; e++) acc[e] = 0.f;
    for (int i = lane; i < In; i += 32) {
        float xv = xr[i];
        const float4* w4 = reinterpret_cast<const float4*>(Wg + (size_t)i * En);
        float4 w0 = w4[0], w1 = w4[1];
        acc[0] += xv * w0.x; acc[1] += xv * w0.y;
        acc[2] += xv * w0.z; acc[3] += xv * w0.w;
        acc[4] += xv * w1.x; acc[5] += xv * w1.y;
        acc[6] += xv * w1.z; acc[7] += xv * w1.w;
    }
#pragma unroll
    for (int e = 0; e < En; e++) {
#pragma unroll
        for (int off = 16; off; off >>= 1)
            acc[e] += __shfl_xor_sync(0xffffffffu, acc[e], off);
    }
    if (lane == 0) {
        float lg[En]; float m = -1e30f;
#pragma unroll
        for (int e = 0; e < En; e++) { lg[e] = acc[e] + bg[e]; m = fmaxf(m, lg[e]); }
        float p[En]; float s = 0.f;
#pragma unroll
        for (int e = 0; e < En; e++) { p[e] = expf(lg[e] - m); s += p[e]; }
#pragma unroll
        for (int e = 0; e < En; e++) p[e] /= s;
        int i0 = 0;
#pragma unroll
        for (int e = 1; e < En; e++) if (p[e] > p[i0]) i0 = e;
        int i1 = (i0 == 0) ? 1 : 0;
#pragma unroll
        for (int e = 0; e < En; e++) if (e != i0 && p[e] > p[i1]) i1 = e;
        float sum2 = p[i0] + p[i1];
        float w0 = p[i0] / sum2, w1 = p[i1] / sum2;
        int s0 = atomicAdd(&g_counts[i0], 1);
        g_tok[i0 * Bn + s0] = b;
        g_pos[b * 2 + 0] = i0 * Bn + s0;
        g_wk[b * 2 + 0] = w0;
        int s1 = atomicAdd(&g_counts[i1], 1);
        g_tok[i1 * Bn + s1] = b;
        g_pos[b * 2 + 1] = i1 * Bn + s1;
        g_wk[b * 2 + 1] = w1;
    }
}

// ---------------- B staging (proven): fp32 W[k][n] -> smem [n][k] bf16 hi/lo ----------------
__device__ __forceinline__ void stage_B_f32(const float* __restrict__ W, size_t Nld,
                                            int kt, int n0, int tid,
                                            char* Bhi, char* Blo) {
    int n = tid & 63, kg = tid >> 6;
    const float* src = W + (size_t)(kt + kg * 8) * Nld + n0 + n;
    float f[8];
#pragma unroll
    for (int j = 0; j < 8; j++) f[j] = src[(size_t)j * Nld];
    uint32_t hi[4], lo[4];
#pragma unroll
    for (int j = 0; j < 4; j++) {
        __nv_bfloat16 h0, l0, h1, l1;
        split_bf16(f[2 * j], h0, l0);
        split_bf16(f[2 * j + 1], h1, l1);
        hi[j] = pack2(h0, h1);
        lo[j] = pack2(l0, l1);
    }
    uint32_t dst = (uint32_t)n * 64 + (uint32_t)((kg ^ SWZ_R(n)) * 16);
    *reinterpret_cast<uint4*>(Bhi + dst) = make_uint4(hi[0], hi[1], hi[2], hi[3]);
    *reinterpret_cast<uint4*>(Blo + dst) = make_uint4(lo[0], lo[1], lo[2], lo[3]);
}

// ---------------- compute via ldmatrix.x4 (proven R10/R11) ----------------
template <int MT, int AP>
__device__ __forceinline__ void compute_tile(uint32_t sbuf, int lane, int warp_m, int warp_n,
                                             float acc[MT][4][4]) {
    uint32_t Ahi = sbuf, Alo = sbuf + AP;
    uint32_t Bhi = sbuf + 2 * AP, Blo = Bhi + PLANE_Bp;
    int rsel = lane & 7, grp = lane >> 3;
#pragma unroll
    for (int ks = 0; ks < 2; ks++) {
        uint32_t bh[4][2], bl[4][2];
#pragma unroll
        for (int p = 0; p < 2; p++) {
            int nt = 2 * p + (grp >> 1);
            int n = warp_n * 32 + nt * 8 + rsel;
            int cB = 2 * ks + (grp & 1);
            uint32_t off = (uint32_t)n * 64 + (uint32_t)((cB ^ SWZ_R(n)) << 4);
            ldsm_x4(bh[2 * p][0], bh[2 * p][1], bh[2 * p + 1][0], bh[2 * p + 1][1], Bhi + off);
            ldsm_x4(bl[2 * p][0], bl[2 * p][1], bl[2 * p + 1][0], bl[2 * p + 1][1], Blo + off);
        }
#pragma unroll
        for (int mt = 0; mt < MT; mt++) {
            int r = warp_m * (MT * 16) + mt * 16 + ((grp & 1) << 3) + rsel;
            int cA = 2 * ks + (grp >> 1);
            uint32_t off = (uint32_t)r * 64 + (uint32_t)((cA ^ SWZ_R(r)) << 4);
            uint32_t ah[4], al[4];
            ldsm_x4(ah[0], ah[1], ah[2], ah[3], Ahi + off);
            ldsm_x4(al[0], al[1], al[2], al[3], Alo + off);
#pragma unroll
            for (int nt = 0; nt < 4; nt++) {
                mma_bf16(acc[mt][nt], ah, bh[nt]);
                mma_bf16(acc[mt][nt], ah, bl[nt]);
                mma_bf16(acc[mt][nt], al, bh[nt]);
            }
        }
    }
}

// ======================= GEMM1 (reverted to R11/R10-proven): M=128, N=64, 2-stage =======================
__global__ void __launch_bounds__(256, 2) gemm1_mma(const float* __restrict__ x,
                                                    const float* __restrict__ W1,
                                                    const float* __restrict__ b1) {
    extern __shared__ char smem[];
    uint32_t sbase = (uint32_t)__cvta_generic_to_shared(smem);
    int tid = threadIdx.x, wid = tid >> 5, lane = tid & 31;
    int warp_m = wid & 3, warp_n = wid >> 2;

    int e = blockIdx.z;
    int count = g_counts[e];
    int m0 = blockIdx.y * 128;
    if (m0 >= count) return;
    int n0 = blockIdx.x * 64;

    const float* W1e = W1 + (size_t)e * In * Hn;
    const int* tokp = g_tok + e * Bn;

    float acc[2][4][4];
#pragma unroll
    for (int i = 0; i < 2; i++)
#pragma unroll
        for (int j = 0; j < 4; j++)
#pragma unroll
            for (int k = 0; k < 4; k++) acc[i][j][k] = 0.f;

    auto fill = [&](char* buf, int kt) {
        char* Ahi = buf; char* Alo = buf + PLANE_A1;
#pragma unroll
        for (int j = 0; j < 2; j++) {
            int idx = tid + j * 256;
            int row = idx >> 2, c = idx & 3;
            int gr = m0 + row;
            int tok = tokp[gr < count ? gr : count - 1];
            const float* srcp = x + (size_t)tok * In + kt + c * 8;
            float4 v0 = *reinterpret_cast<const float4*>(srcp);
            float4 v1 = *reinterpret_cast<const float4*>(srcp + 4);
            float f[8] = {v0.x, v0.y, v0.z, v0.w, v1.x, v1.y, v1.z, v1.w};
            uint32_t hi[4], lo[4];
#pragma unroll
            for (int q = 0; q < 4; q++) {
                __nv_bfloat16 h0, l0, h1, l1;
                split_bf16(f[2 * q], h0, l0);
                split_bf16(f[2 * q + 1], h1, l1);
                hi[q] = pack2(h0, h1);
                lo[q] = pack2(l0, l1);
            }
            uint32_t dst = (uint32_t)row * 64 + (uint32_t)((c ^ SWZ_R(row)) * 16);
            *reinterpret_cast<uint4*>(Ahi + dst) = make_uint4(hi[0], hi[1], hi[2], hi[3]);
            *reinterpret_cast<uint4*>(Alo + dst) = make_uint4(lo[0], lo[1], lo[2], lo[3]);
        }
        stage_B_f32(W1e, Hn, kt, n0, tid, buf + 2 * PLANE_A1, buf + 2 * PLANE_A1 + PLANE_Bp);
    };

    const int NC = In / 32;    // 16
    fill(smem, 0);
    __syncthreads();
    for (int c = 0; c < NC; c++) {
        uint32_t curo = (c & 1) ? BUF1_B : 0;
        char* nxt = smem + ((c & 1) ? 0 : BUF1_B);
        if (c + 1 < NC) fill(nxt, (c + 1) * 32);
        compute_tile<2, PLANE_A1>(sbase + curo, lane, warp_m, warp_n, acc);
        __syncthreads();
    }

#pragma unroll
    for (int mt = 0; mt < 2; mt++) {
        int row_l = warp_m * 32 + mt * 16 + (lane >> 2);
#pragma unroll
        for (int nt = 0; nt < 4; nt++) {
            int ncol_l = warp_n * 32 + nt * 8 + (lane & 3) * 2;
            float bb0 = b1[e * Hn + n0 + ncol_l];
            float bb1 = b1[e * Hn + n0 + ncol_l + 1];
#pragma unroll
            for (int h = 0; h < 2; h++) {
                int grow = m0 + row_l + h * 8;
                float v0 = fmaxf(acc[mt][nt][h * 2 + 0] + bb0, 0.f);
                float v1 = fmaxf(acc[mt][nt][h * 2 + 1] + bb1, 0.f);
                __nv_bfloat16 h0, h1, l0, l1;
                split_bf16(v0, h0, l0); split_bf16(v1, h1, l1);
                size_t off = (size_t)(e * Bn + grow) * Hn + n0 + ncol_l;
                *reinterpret_cast<uint32_t*>(g_hhi + off) = pack2(h0, h1);
                *reinterpret_cast<uint32_t*>(g_hlo + off) = pack2(l0, l1);
            }
        }
    }
}

// ======================= GEMM2: K-split-2, 3-stage pipeline, cp.async A (R11 core) =======================
// M=64, N=64. blockIdx.y = (m_tile << 1) | k_half. Each block does K/2 = 1024 (32 iters).
__global__ void __launch_bounds__(256, 2) gemm2_mma(const float* __restrict__ W2) {
    extern __shared__ char smem[];
    uint32_t sbase = (uint32_t)__cvta_generic_to_shared(smem);
    int tid = threadIdx.x, wid = tid >> 5, lane = tid & 31;
    int warp_m = wid & 3, warp_n = wid >> 2;

    int e = blockIdx.z;
    int count = g_counts[e];
    int kh = blockIdx.y & 1;
    int m0 = (blockIdx.y >> 1) * 64;
    if (m0 >= count) return;
    int n0 = blockIdx.x * 64;
    int kbase = kh * (Hn / 2);                 // 0 or 1024

    const __nv_bfloat16* Ahg = g_hhi + (size_t)(e * Bn + m0) * Hn + kbase;
    const __nv_bfloat16* Alg = g_hlo + (size_t)(e * Bn + m0) * Hn + kbase;
    const float* W2e = W2 + (size_t)e * Hn * On + (size_t)kbase * On;
    float* yout = (kh ? g_y2 : g_y);

    float acc[1][4][4];
#pragma unroll
    for (int j = 0; j < 4; j++)
#pragma unroll
        for (int k = 0; k < 4; k++) acc[0][j][k] = 0.f;

    int arow = tid >> 2, ach = tid & 3;
    uint32_t adst = (uint32_t)arow * 64 + (uint32_t)((ach ^ SWZ_R(arow)) * 16);
    int bn = tid & 63, bkg = tid >> 6;
    uint32_t bdst = (uint32_t)bn * 64 + (uint32_t)((bkg ^ SWZ_R(bn)) * 16);

    float fB[8];

    auto aload = [&](int b, int kt) {
        size_t src = (size_t)arow * Hn + kt + ach * 8;
        uint32_t d = sbase + (uint32_t)(b * BUF2_B) + adst;
        CP16(d, Ahg + src);
        CP16(d + PLANE_A2, Alg + src);
    };
    auto bload = [&](int kt) {
        const float* src = W2e + (size_t)(kt + bkg * 8) * On + n0 + bn;
#pragma unroll
        for (int j = 0; j < 8; j++) fB[j] = src[(size_t)j * On];
    };
    auto bstore = [&](int b) {
        uint32_t hi[4], lo[4];
#pragma unroll
        for (int j = 0; j < 4; j++) {
            __nv_bfloat16 h0, l0, h1, l1;
            split_bf16(fB[2 * j], h0, l0);
            split_bf16(fB[2 * j + 1], h1, l1);
            hi[j] = pack2(h0, h1);
            lo[j] = pack2(l0, l1);
        }
        char* base = smem + b * BUF2_B + 2 * PLANE_A2;
        *reinterpret_cast<uint4*>(base + bdst)            = make_uint4(hi[0], hi[1], hi[2], hi[3]);
        *reinterpret_cast<uint4*>(base + PLANE_Bp + bdst) = make_uint4(lo[0], lo[1], lo[2], lo[3]);
    };

    const int NC = (Hn / 2) / 32;    // 32

    bload(0);  aload(0, 0);  CPCOMMIT(); bstore(0);
    bload(32); aload(1, 32); CPCOMMIT(); bstore(1);

    for (int c = 0; c < NC; c++) {
        if (c + 1 < NC) { CPWAIT1(); } else { CPWAIT0(); }
        __syncthreads();
        bool pre = (c + 2 < NC);
        if (pre) {
            int kt2 = (c + 2) * 32;
            bload(kt2);
            aload((c + 2) % 3, kt2);
            CPCOMMIT();
        }
        compute_tile<1, PLANE_A2>(sbase + (uint32_t)((c % 3) * BUF2_B), lane, warp_m, warp_n, acc);
        if (pre) bstore((c + 2) % 3);
    }

#pragma unroll
    for (int nt = 0; nt < 4; nt++) {
        int ncol_l = warp_n * 32 + nt * 8 + (lane & 3) * 2;
#pragma unroll
        for (int h = 0; h < 2; h++) {
            int grow = m0 + warp_m * 16 + (lane >> 2) + h * 8;
            float2 v = make_float2(acc[0][nt][h * 2 + 0], acc[0][nt][h * 2 + 1]);
            *reinterpret_cast<float2*>(yout + (size_t)(e * Bn + grow) * On + n0 + ncol_l) = v;
        }
    }
}

// ---------------- combine (+ b2), sums the two K-halves ----------------
__global__ void combine_kernel(const float* __restrict__ b2, float* __restrict__ out) {
    int idx = blockIdx.x * 256 + threadIdx.x;
    int b = idx >> 7;
    int o = (idx & 127) * 4;
    int p0 = g_pos[b * 2 + 0], p1 = g_pos[b * 2 + 1];
    float w0 = g_wk[b * 2 + 0], w1 = g_wk[b * 2 + 1];
    int e0 = p0 >> 10, e1 = p1 >> 10;
    float4 ya0 = *reinterpret_cast<const float4*>(g_y  + (size_t)p0 * On + o);
    float4 yb0 = *reinterpret_cast<const float4*>(g_y2 + (size_t)p0 * On + o);
    float4 ya1 = *reinterpret_cast<const float4*>(g_y  + (size_t)p1 * On + o);
    float4 yb1 = *reinterpret_cast<const float4*>(g_y2 + (size_t)p1 * On + o);
    float4 c0 = *reinterpret_cast<const float4*>(b2 + (size_t)e0 * On + o);
    float4 c1 = *reinterpret_cast<const float4*>(b2 + (size_t)e1 * On + o);
    float4 r;
    r.x = w0 * (ya0.x + yb0.x + c0.x) + w1 * (ya1.x + yb1.x + c1.x);
    r.y = w0 * (ya0.y + yb0.y + c0.y) + w1 * (ya1.y + yb1.y + c1.y);
    r.z = w0 * (ya0.z + yb0.z + c0.z) + w1 * (ya1.z + yb1.z + c1.z);
    r.w = w0 * (ya0.w + yb0.w + c0.w) + w1 * (ya1.w + yb1.w + c1.w);
    *reinterpret_cast<float4*>(out + (size_t)b * On + o) = r;
}

// ---------------- launch ----------------
extern "C" void kernel_launch(void* const* d_in, const int* in_sizes, int n_in,
                              void* d_out, int out_size) {
    const float* x  = (const float*)d_in[0];
    const float* Wg = (const float*)d_in[1];
    const float* bg = (const float*)d_in[2];
    const float* W1 = (const float*)d_in[3];
    const float* b1 = (const float*)d_in[4];
    const float* W2 = (const float*)d_in[5];
    const float* b2 = (const float*)d_in[6];
    float* out = (float*)d_out;

    zero_counts_kernel<<<1, 32>>>();
    gate_kernel<<<Bn / 8, 256>>>(x, Wg, bg);
    gemm1_mma<<<dim3(Hn / 64, Bn / 128, En), 256, GSMEM1>>>(x, W1, b1);
    gemm2_mma<<<dim3(On / 64, (Bn / 64) * 2, En), 256, GSMEM2>>>(W2);
    combine_kernel<<<(Bn * On / 4) / 256, 256>>>(b2, out);
}

// round 14
// speedup vs baseline: 1.1119x; 1.0384x over previous
#include <cuda_runtime.h>
#include <cuda_bf16.h>
#include <math.h>
#include <stdint.h>

#define Bn 1024
#define In 512
#define Hn 2048
#define On 512
#define En 8

// ---------------- scratch (device globals; zero-init, 16B aligned; ~96MB) ----------------
__device__ __align__(16) int   g_counts[En];
__device__ __align__(16) int   g_tok[En * Bn];
__device__ __align__(16) int   g_pos[Bn * 2];
__device__ __align__(16) float g_wk[Bn * 2];
__device__ __align__(16) __nv_bfloat16 g_hhi[En * Bn * Hn];   // 32 MB
__device__ __align__(16) __nv_bfloat16 g_hlo[En * Bn * Hn];   // 32 MB
__device__ __align__(16) float g_y[En * Bn * On];             // 16 MB (K-half 0)
__device__ __align__(16) float g_y2[En * Bn * On];            // 16 MB (K-half 1)

// ---------------- mma / ldmatrix / cp.async helpers ----------------
__device__ __forceinline__ void mma_bf16(float* c, const uint32_t* a, const uint32_t* b) {
    asm volatile(
        "mma.sync.aligned.m16n8k16.row.col.f32.bf16.bf16.f32 "
        "{%0,%1,%2,%3}, {%4,%5,%6,%7}, {%8,%9}, {%0,%1,%2,%3};"
        : "+f"(c[0]), "+f"(c[1]), "+f"(c[2]), "+f"(c[3])
        : "r"(a[0]), "r"(a[1]), "r"(a[2]), "r"(a[3]), "r"(b[0]), "r"(b[1]));
}
__device__ __forceinline__ void ldsm_x4(uint32_t& r0, uint32_t& r1, uint32_t& r2, uint32_t& r3,
                                        uint32_t addr) {
    asm volatile("ldmatrix.sync.aligned.m8n8.x4.shared.b16 {%0,%1,%2,%3}, [%4];"
        : "=r"(r0), "=r"(r1), "=r"(r2), "=r"(r3) : "r"(addr));
}
#define CP16(dst, src) asm volatile("cp.async.cg.shared.global [%0], [%1], 16;" :: "r"(dst), "l"(src))
#define CPCOMMIT()     asm volatile("cp.async.commit_group;" ::: "memory")
#define CPWAIT1()      asm volatile("cp.async.wait_group 1;" ::: "memory")
#define CPWAIT0()      asm volatile("cp.async.wait_group 0;" ::: "memory")

__device__ __forceinline__ void split_bf16(float v, __nv_bfloat16& h, __nv_bfloat16& l) {
    h = __float2bfloat16(v);
    l = __float2bfloat16(v - __bfloat162float(h));
}
__device__ __forceinline__ uint32_t pack2(__nv_bfloat16 a, __nv_bfloat16 b) {
    return ((uint32_t)__bfloat16_as_ushort(b) << 16) | __bfloat16_as_ushort(a);
}

// ---------------- pad-free swizzled smem planes (proven R9-R13) ----------------
#define PLANE_Bp 4096                 // 64 rows
#define SWZ_R(r) (((r) >> 1) & 3)

#define PLANE_A1 8192                 // gemm1 A: 128 rows
#define BUF1_B   (2 * PLANE_A1 + 2 * PLANE_Bp)   // 24576
#define GSMEM1   (2 * BUF1_B)                    // 49152

#define PLANE_A2 4096                 // gemm2 A: 64 rows
#define BUF2_B   (2 * PLANE_A2 + 2 * PLANE_Bp)   // 16384
#define GSMEM2   (3 * BUF2_B)                    // 49152 triple buffer

// ---------------- kernel 0: zero counters ----------------
__global__ void zero_counts_kernel() {
    if (threadIdx.x < En) g_counts[threadIdx.x] = 0;
}

// ---------------- kernel 1: gating (proven) ----------------
__global__ void gate_kernel(const float* __restrict__ x,
                            const float* __restrict__ Wg,
                            const float* __restrict__ bg) {
    int warp = threadIdx.x >> 5, lane = threadIdx.x & 31;
    int b = blockIdx.x * 8 + warp;
    const float* xr = x + (size_t)b * In;

    float acc[En];
#pragma unroll
    for (int e = 0; e < En; e++) acc[e] = 0.f;
    for (int i = lane; i < In; i += 32) {
        float xv = xr[i];
        const float4* w4 = reinterpret_cast<const float4*>(Wg + (size_t)i * En);
        float4 w0 = w4[0], w1 = w4[1];
        acc[0] += xv * w0.x; acc[1] += xv * w0.y;
        acc[2] += xv * w0.z; acc[3] += xv * w0.w;
        acc[4] += xv * w1.x; acc[5] += xv * w1.y;
        acc[6] += xv * w1.z; acc[7] += xv * w1.w;
    }
#pragma unroll
    for (int e = 0; e < En; e++) {
#pragma unroll
        for (int off = 16; off; off >>= 1)
            acc[e] += __shfl_xor_sync(0xffffffffu, acc[e], off);
    }
    if (lane == 0) {
        float lg[En]; float m = -1e30f;
#pragma unroll
        for (int e = 0; e < En; e++) { lg[e] = acc[e] + bg[e]; m = fmaxf(m, lg[e]); }
        float p[En]; float s = 0.f;
#pragma unroll
        for (int e = 0; e < En; e++) { p[e] = expf(lg[e] - m); s += p[e]; }
#pragma unroll
        for (int e = 0; e < En; e++) p[e] /= s;
        int i0 = 0;
#pragma unroll
        for (int e = 1; e < En; e++) if (p[e] > p[i0]) i0 = e;
        int i1 = (i0 == 0) ? 1 : 0;
#pragma unroll
        for (int e = 0; e < En; e++) if (e != i0 && p[e] > p[i1]) i1 = e;
        float sum2 = p[i0] + p[i1];
        float w0 = p[i0] / sum2, w1 = p[i1] / sum2;
        int s0 = atomicAdd(&g_counts[i0], 1);
        g_tok[i0 * Bn + s0] = b;
        g_pos[b * 2 + 0] = i0 * Bn + s0;
        g_wk[b * 2 + 0] = w0;
        int s1 = atomicAdd(&g_counts[i1], 1);
        g_tok[i1 * Bn + s1] = b;
        g_pos[b * 2 + 1] = i1 * Bn + s1;
        g_wk[b * 2 + 1] = w1;
    }
}

// ---------------- compute via ldmatrix.x4 (proven R10-R13) ----------------
template <int MT, int AP>
__device__ __forceinline__ void compute_tile(uint32_t sbuf, int lane, int warp_m, int warp_n,
                                             float acc[MT][4][4]) {
    uint32_t Ahi = sbuf, Alo = sbuf + AP;
    uint32_t Bhi = sbuf + 2 * AP, Blo = Bhi + PLANE_Bp;
    int rsel = lane & 7, grp = lane >> 3;
#pragma unroll
    for (int ks = 0; ks < 2; ks++) {
        uint32_t bh[4][2], bl[4][2];
#pragma unroll
        for (int p = 0; p < 2; p++) {
            int nt = 2 * p + (grp >> 1);
            int n = warp_n * 32 + nt * 8 + rsel;
            int cB = 2 * ks + (grp & 1);
            uint32_t off = (uint32_t)n * 64 + (uint32_t)((cB ^ SWZ_R(n)) << 4);
            ldsm_x4(bh[2 * p][0], bh[2 * p][1], bh[2 * p + 1][0], bh[2 * p + 1][1], Bhi + off);
            ldsm_x4(bl[2 * p][0], bl[2 * p][1], bl[2 * p + 1][0], bl[2 * p + 1][1], Blo + off);
        }
#pragma unroll
        for (int mt = 0; mt < MT; mt++) {
            int r = warp_m * (MT * 16) + mt * 16 + ((grp & 1) << 3) + rsel;
            int cA = 2 * ks + (grp >> 1);
            uint32_t off = (uint32_t)r * 64 + (uint32_t)((cA ^ SWZ_R(r)) << 4);
            uint32_t ah[4], al[4];
            ldsm_x4(ah[0], ah[1], ah[2], ah[3], Ahi + off);
            ldsm_x4(al[0], al[1], al[2], al[3], Alo + off);
#pragma unroll
            for (int nt = 0; nt < 4; nt++) {
                mma_bf16(acc[mt][nt], ah, bh[nt]);
                mma_bf16(acc[mt][nt], ah, bl[nt]);
                mma_bf16(acc[mt][nt], al, bh[nt]);
            }
        }
    }
}

// ======================= GEMM1: M=128/N=64, double buffer + split-load pipeline =======================
__global__ void __launch_bounds__(256, 2) gemm1_mma(const float* __restrict__ x,
                                                    const float* __restrict__ W1,
                                                    const float* __restrict__ b1) {
    extern __shared__ char smem[];
    uint32_t sbase = (uint32_t)__cvta_generic_to_shared(smem);
    int tid = threadIdx.x, wid = tid >> 5, lane = tid & 31;
    int warp_m = wid & 3, warp_n = wid >> 2;

    int e = blockIdx.z;
    int count = g_counts[e];
    int m0 = blockIdx.y * 128;
    if (m0 >= count) return;
    int n0 = blockIdx.x * 64;

    const float* W1e = W1 + (size_t)e * In * Hn;
    const int* tokp = g_tok + e * Bn;

    float acc[2][4][4];
#pragma unroll
    for (int i = 0; i < 2; i++)
#pragma unroll
        for (int j = 0; j < 4; j++)
#pragma unroll
            for (int k = 0; k < 4; k++) acc[i][j][k] = 0.f;

    // A: two rows per thread (arow0 and arow0+64), chunk ach of 8 floats
    int arow0 = tid >> 2, ach = tid & 3;
    int gr0 = m0 + arow0, gr1 = m0 + arow0 + 64;
    int tok0 = tokp[gr0 < count ? gr0 : count - 1];
    int tok1 = tokp[gr1 < count ? gr1 : count - 1];
    const float* Asrc0 = x + (size_t)tok0 * In + ach * 8;
    const float* Asrc1 = x + (size_t)tok1 * In + ach * 8;
    uint32_t adst0 = (uint32_t)arow0 * 64 + (uint32_t)((ach ^ SWZ_R(arow0)) * 16);
    uint32_t adst1 = (uint32_t)(arow0 + 64) * 64 + (uint32_t)((ach ^ SWZ_R(arow0 + 64)) * 16);
    // B: n = tid&63, k-group = tid>>6
    int bn = tid & 63, bkg = tid >> 6;
    uint32_t bdst = (uint32_t)bn * 64 + (uint32_t)((bkg ^ SWZ_R(bn)) * 16);

    float fA[16], fB[8];

    auto ld = [&](int kt) {
        float4 v0 = *reinterpret_cast<const float4*>(Asrc0 + kt);
        float4 v1 = *reinterpret_cast<const float4*>(Asrc0 + kt + 4);
        fA[0] = v0.x; fA[1] = v0.y; fA[2] = v0.z; fA[3] = v0.w;
        fA[4] = v1.x; fA[5] = v1.y; fA[6] = v1.z; fA[7] = v1.w;
        float4 v2 = *reinterpret_cast<const float4*>(Asrc1 + kt);
        float4 v3 = *reinterpret_cast<const float4*>(Asrc1 + kt + 4);
        fA[8] = v2.x; fA[9] = v2.y; fA[10] = v2.z; fA[11] = v2.w;
        fA[12] = v3.x; fA[13] = v3.y; fA[14] = v3.z; fA[15] = v3.w;
        const float* src = W1e + (size_t)(kt + bkg * 8) * Hn + n0 + bn;
#pragma unroll
        for (int j = 0; j < 8; j++) fB[j] = src[(size_t)j * Hn];
    };
    auto st = [&](int b) {
        char* base = smem + b * BUF1_B;
        uint32_t hi[4], lo[4];
#pragma unroll
        for (int half = 0; half < 2; half++) {
#pragma unroll
            for (int j = 0; j < 4; j++) {
                __nv_bfloat16 h0, l0, h1, l1;
                split_bf16(fA[half * 8 + 2 * j], h0, l0);
                split_bf16(fA[half * 8 + 2 * j + 1], h1, l1);
                hi[j] = pack2(h0, h1); lo[j] = pack2(l0, l1);
            }
            uint32_t ad = half ? adst1 : adst0;
            *reinterpret_cast<uint4*>(base + ad)            = make_uint4(hi[0], hi[1], hi[2], hi[3]);
            *reinterpret_cast<uint4*>(base + PLANE_A1 + ad) = make_uint4(lo[0], lo[1], lo[2], lo[3]);
        }
#pragma unroll
        for (int j = 0; j < 4; j++) {
            __nv_bfloat16 h0, l0, h1, l1;
            split_bf16(fB[2 * j], h0, l0);
            split_bf16(fB[2 * j + 1], h1, l1);
            hi[j] = pack2(h0, h1); lo[j] = pack2(l0, l1);
        }
        *reinterpret_cast<uint4*>(base + 2 * PLANE_A1 + bdst)            = make_uint4(hi[0], hi[1], hi[2], hi[3]);
        *reinterpret_cast<uint4*>(base + 2 * PLANE_A1 + PLANE_Bp + bdst) = make_uint4(lo[0], lo[1], lo[2], lo[3]);
    };

    const int NC = In / 32;    // 16
    ld(0); st(0);
    __syncthreads();
    for (int c = 0; c < NC; c++) {
        bool pre = (c + 1 < NC);
        if (pre) ld((c + 1) * 32);                      // LDGs in flight during compute
        compute_tile<2, PLANE_A1>(sbase + (uint32_t)((c & 1) * BUF1_B), lane, warp_m, warp_n, acc);
        if (pre) st((c + 1) & 1);                       // convert + STS after compute
        __syncthreads();
    }

    // epilogue: +bias, ReLU, split -> g_hhi/g_hlo
#pragma unroll
    for (int mt = 0; mt < 2; mt++) {
        int row_l = warp_m * 32 + mt * 16 + (lane >> 2);
#pragma unroll
        for (int nt = 0; nt < 4; nt++) {
            int ncol_l = warp_n * 32 + nt * 8 + (lane & 3) * 2;
            float bb0 = b1[e * Hn + n0 + ncol_l];
            float bb1 = b1[e * Hn + n0 + ncol_l + 1];
#pragma unroll
            for (int h = 0; h < 2; h++) {
                int grow = m0 + row_l + h * 8;
                float v0 = fmaxf(acc[mt][nt][h * 2 + 0] + bb0, 0.f);
                float v1 = fmaxf(acc[mt][nt][h * 2 + 1] + bb1, 0.f);
                __nv_bfloat16 h0, h1, l0, l1;
                split_bf16(v0, h0, l0); split_bf16(v1, h1, l1);
                size_t off = (size_t)(e * Bn + grow) * Hn + n0 + ncol_l;
                *reinterpret_cast<uint32_t*>(g_hhi + off) = pack2(h0, h1);
                *reinterpret_cast<uint32_t*>(g_hlo + off) = pack2(l0, l1);
            }
        }
    }
}

// ======================= GEMM2: K-split-2, 3-stage pipeline, cp.async A — now 3 CTAs/SM =======================
__global__ void __launch_bounds__(256, 3) gemm2_mma(const float* __restrict__ W2) {
    extern __shared__ char smem[];
    uint32_t sbase = (uint32_t)__cvta_generic_to_shared(smem);
    int tid = threadIdx.x, wid = tid >> 5, lane = tid & 31;
    int warp_m = wid & 3, warp_n = wid >> 2;

    int e = blockIdx.z;
    int count = g_counts[e];
    int kh = blockIdx.y & 1;
    int m0 = (blockIdx.y >> 1) * 64;
    if (m0 >= count) return;
    int n0 = blockIdx.x * 64;
    int kbase = kh * (Hn / 2);

    const __nv_bfloat16* Ahg = g_hhi + (size_t)(e * Bn + m0) * Hn + kbase;
    const __nv_bfloat16* Alg = g_hlo + (size_t)(e * Bn + m0) * Hn + kbase;
    const float* W2e = W2 + (size_t)e * Hn * On + (size_t)kbase * On;
    float* yout = (kh ? g_y2 : g_y);

    float acc[1][4][4];
#pragma unroll
    for (int j = 0; j < 4; j++)
#pragma unroll
        for (int k = 0; k < 4; k++) acc[0][j][k] = 0.f;

    int arow = tid >> 2, ach = tid & 3;
    uint32_t adst = (uint32_t)arow * 64 + (uint32_t)((ach ^ SWZ_R(arow)) * 16);
    int bn = tid & 63, bkg = tid >> 6;
    uint32_t bdst = (uint32_t)bn * 64 + (uint32_t)((bkg ^ SWZ_R(bn)) * 16);

    float fB[8];

    auto aload = [&](int b, int kt) {
        size_t src = (size_t)arow * Hn + kt + ach * 8;
        uint32_t d = sbase + (uint32_t)(b * BUF2_B) + adst;
        CP16(d, Ahg + src);
        CP16(d + PLANE_A2, Alg + src);
    };
    auto bload = [&](int kt) {
        const float* src = W2e + (size_t)(kt + bkg * 8) * On + n0 + bn;
#pragma unroll
        for (int j = 0; j < 8; j++) fB[j] = src[(size_t)j * On];
    };
    auto bstore = [&](int b) {
        uint32_t hi[4], lo[4];
#pragma unroll
        for (int j = 0; j < 4; j++) {
            __nv_bfloat16 h0, l0, h1, l1;
            split_bf16(fB[2 * j], h0, l0);
            split_bf16(fB[2 * j + 1], h1, l1);
            hi[j] = pack2(h0, h1);
            lo[j] = pack2(l0, l1);
        }
        char* base = smem + b * BUF2_B + 2 * PLANE_A2;
        *reinterpret_cast<uint4*>(base + bdst)            = make_uint4(hi[0], hi[1], hi[2], hi[3]);
        *reinterpret_cast<uint4*>(base + PLANE_Bp + bdst) = make_uint4(lo[0], lo[1], lo[2], lo[3]);
    };

    const int NC = (Hn / 2) / 32;    // 32

    bload(0);  aload(0, 0);  CPCOMMIT(); bstore(0);
    bload(32); aload(1, 32); CPCOMMIT(); bstore(1);

    for (int c = 0; c < NC; c++) {
        if (c + 1 < NC) { CPWAIT1(); } else { CPWAIT0(); }
        __syncthreads();
        bool pre = (c + 2 < NC);
        if (pre) {
            int kt2 = (c + 2) * 32;
            bload(kt2);
            aload((c + 2) % 3, kt2);
            CPCOMMIT();
        }
        compute_tile<1, PLANE_A2>(sbase + (uint32_t)((c % 3) * BUF2_B), lane, warp_m, warp_n, acc);
        if (pre) bstore((c + 2) % 3);
    }

#pragma unroll
    for (int nt = 0; nt < 4; nt++) {
        int ncol_l = warp_n * 32 + nt * 8 + (lane & 3) * 2;
#pragma unroll
        for (int h = 0; h < 2; h++) {
            int grow = m0 + warp_m * 16 + (lane >> 2) + h * 8;
            float2 v = make_float2(acc[0][nt][h * 2 + 0], acc[0][nt][h * 2 + 1]);
            *reinterpret_cast<float2*>(yout + (size_t)(e * Bn + grow) * On + n0 + ncol_l) = v;
        }
    }
}

// ---------------- combine (+ b2), sums the two K-halves ----------------
__global__ void combine_kernel(const float* __restrict__ b2, float* __restrict__ out) {
    int idx = blockIdx.x * 256 + threadIdx.x;
    int b = idx >> 7;
    int o = (idx & 127) * 4;
    int p0 = g_pos[b * 2 + 0], p1 = g_pos[b * 2 + 1];
    float w0 = g_wk[b * 2 + 0], w1 = g_wk[b * 2 + 1];
    int e0 = p0 >> 10, e1 = p1 >> 10;
    float4 ya0 = *reinterpret_cast<const float4*>(g_y  + (size_t)p0 * On + o);
    float4 yb0 = *reinterpret_cast<const float4*>(g_y2 + (size_t)p0 * On + o);
    float4 ya1 = *reinterpret_cast<const float4*>(g_y  + (size_t)p1 * On + o);
    float4 yb1 = *reinterpret_cast<const float4*>(g_y2 + (size_t)p1 * On + o);
    float4 c0 = *reinterpret_cast<const float4*>(b2 + (size_t)e0 * On + o);
    float4 c1 = *reinterpret_cast<const float4*>(b2 + (size_t)e1 * On + o);
    float4 r;
    r.x = w0 * (ya0.x + yb0.x + c0.x) + w1 * (ya1.x + yb1.x + c1.x);
    r.y = w0 * (ya0.y + yb0.y + c0.y) + w1 * (ya1.y + yb1.y + c1.y);
    r.z = w0 * (ya0.z + yb0.z + c0.z) + w1 * (ya1.z + yb1.z + c1.z);
    r.w = w0 * (ya0.w + yb0.w + c0.w) + w1 * (ya1.w + yb1.w + c1.w);
    *reinterpret_cast<float4*>(out + (size_t)b * On + o) = r;
}

// ---------------- launch ----------------
extern "C" void kernel_launch(void* const* d_in, const int* in_sizes, int n_in,
                              void* d_out, int out_size) {
    const float* x  = (const float*)d_in[0];
    const float* Wg = (const float*)d_in[1];
    const float* bg = (const float*)d_in[2];
    const float* W1 = (const float*)d_in[3];
    const float* b1 = (const float*)d_in[4];
    const float* W2 = (const float*)d_in[5];
    const float* b2 = (const float*)d_in[6];
    float* out = (float*)d_out;

    zero_counts_kernel<<<1, 32>>>();
    gate_kernel<<<Bn / 8, 256>>>(x, Wg, bg);
    gemm1_mma<<<dim3(Hn / 64, Bn / 128, En), 256, GSMEM1>>>(x, W1, b1);
    gemm2_mma<<<dim3(On / 64, (Bn / 64) * 2, En), 256, GSMEM2>>>(W2);
    combine_kernel<<<(Bn * On / 4) / 256, 256>>>(b2, out);
}

// round 15
// speedup vs baseline: 1.4479x; 1.3022x over previous
#include <cuda_runtime.h>
#include <cuda_bf16.h>
#include <cuda_fp16.h>
#include <math.h>
#include <stdint.h>

#define Bn 1024
#define In 512
#define Hn 2048
#define On 512
#define En 8

// ---------------- scratch (device globals; zero-init, 16B aligned; ~64MB) ----------------
__device__ __align__(16) int   g_counts[En];
__device__ __align__(16) int   g_tok[En * Bn];
__device__ __align__(16) int   g_pos[Bn * 2];
__device__ __align__(16) float g_wk[Bn * 2];
__device__ __align__(16) __half g_hf16[En * Bn * Hn];        // 32 MB (fp16 hidden)
__device__ __align__(16) float g_y[En * Bn * On];            // 16 MB (K-half 0)
__device__ __align__(16) float g_y2[En * Bn * On];           // 16 MB (K-half 1)

// ---------------- mma / ldmatrix / cp.async helpers ----------------
__device__ __forceinline__ void mma_bf16(float* c, const uint32_t* a, const uint32_t* b) {
    asm volatile(
        "mma.sync.aligned.m16n8k16.row.col.f32.bf16.bf16.f32 "
        "{%0,%1,%2,%3}, {%4,%5,%6,%7}, {%8,%9}, {%0,%1,%2,%3};"
        : "+f"(c[0]), "+f"(c[1]), "+f"(c[2]), "+f"(c[3])
        : "r"(a[0]), "r"(a[1]), "r"(a[2]), "r"(a[3]), "r"(b[0]), "r"(b[1]));
}
__device__ __forceinline__ void mma_f16(float* c, const uint32_t* a, const uint32_t* b) {
    asm volatile(
        "mma.sync.aligned.m16n8k16.row.col.f32.f16.f16.f32 "
        "{%0,%1,%2,%3}, {%4,%5,%6,%7}, {%8,%9}, {%0,%1,%2,%3};"
        : "+f"(c[0]), "+f"(c[1]), "+f"(c[2]), "+f"(c[3])
        : "r"(a[0]), "r"(a[1]), "r"(a[2]), "r"(a[3]), "r"(b[0]), "r"(b[1]));
}
__device__ __forceinline__ void ldsm_x4(uint32_t& r0, uint32_t& r1, uint32_t& r2, uint32_t& r3,
                                        uint32_t addr) {
    asm volatile("ldmatrix.sync.aligned.m8n8.x4.shared.b16 {%0,%1,%2,%3}, [%4];"
        : "=r"(r0), "=r"(r1), "=r"(r2), "=r"(r3) : "r"(addr));
}
#define CP16(dst, src) asm volatile("cp.async.cg.shared.global [%0], [%1], 16;" :: "r"(dst), "l"(src))
#define CPCOMMIT()     asm volatile("cp.async.commit_group;" ::: "memory")
#define CPWAIT1()      asm volatile("cp.async.wait_group 1;" ::: "memory")
#define CPWAIT0()      asm volatile("cp.async.wait_group 0;" ::: "memory")

__device__ __forceinline__ void split_bf16(float v, __nv_bfloat16& h, __nv_bfloat16& l) {
    h = __float2bfloat16(v);
    l = __float2bfloat16(v - __bfloat162float(h));
}
__device__ __forceinline__ uint32_t pack2(__nv_bfloat16 a, __nv_bfloat16 b) {
    return ((uint32_t)__bfloat16_as_ushort(b) << 16) | __bfloat16_as_ushort(a);
}
__device__ __forceinline__ uint32_t pack2h(float a, float b) {
    __half2 v = __floats2half2_rn(a, b);
    return *reinterpret_cast<uint32_t*>(&v);
}

// ---------------- pad-free swizzled smem planes (proven R9-R14) ----------------
#define PLANE_Bp 4096                 // 64 rows x 64 B
#define SWZ_R(r) (((r) >> 1) & 3)

#define PLANE_A1 8192                 // gemm1 A: 128 rows
#define BUF1_B   (2 * PLANE_A1 + 2 * PLANE_Bp)   // 24576
#define GSMEM1   (2 * BUF1_B)                    // 49152

#define BUF2_B   (2 * PLANE_Bp)       // gemm2: A_f16 + B_f16 = 8192
#define GSMEM2   (3 * BUF2_B)         // 24576 triple buffer

// ---------------- kernel 0: zero counters ----------------
__global__ void zero_counts_kernel() {
    if (threadIdx.x < En) g_counts[threadIdx.x] = 0;
}

// ---------------- kernel 1: gating (proven) ----------------
__global__ void gate_kernel(const float* __restrict__ x,
                            const float* __restrict__ Wg,
                            const float* __restrict__ bg) {
    int warp = threadIdx.x >> 5, lane = threadIdx.x & 31;
    int b = blockIdx.x * 8 + warp;
    const float* xr = x + (size_t)b * In;

    float acc[En];
#pragma unroll
    for (int e = 0; e < En; e++) acc[e] = 0.f;
    for (int i = lane; i < In; i += 32) {
        float xv = xr[i];
        const float4* w4 = reinterpret_cast<const float4*>(Wg + (size_t)i * En);
        float4 w0 = w4[0], w1 = w4[1];
        acc[0] += xv * w0.x; acc[1] += xv * w0.y;
        acc[2] += xv * w0.z; acc[3] += xv * w0.w;
        acc[4] += xv * w1.x; acc[5] += xv * w1.y;
        acc[6] += xv * w1.z; acc[7] += xv * w1.w;
    }
#pragma unroll
    for (int e = 0; e < En; e++) {
#pragma unroll
        for (int off = 16; off; off >>= 1)
            acc[e] += __shfl_xor_sync(0xffffffffu, acc[e], off);
    }
    if (lane == 0) {
        float lg[En]; float m = -1e30f;
#pragma unroll
        for (int e = 0; e < En; e++) { lg[e] = acc[e] + bg[e]; m = fmaxf(m, lg[e]); }
        float p[En]; float s = 0.f;
#pragma unroll
        for (int e = 0; e < En; e++) { p[e] = expf(lg[e] - m); s += p[e]; }
#pragma unroll
        for (int e = 0; e < En; e++) p[e] /= s;
        int i0 = 0;
#pragma unroll
        for (int e = 1; e < En; e++) if (p[e] > p[i0]) i0 = e;
        int i1 = (i0 == 0) ? 1 : 0;
#pragma unroll
        for (int e = 0; e < En; e++) if (e != i0 && p[e] > p[i1]) i1 = e;
        float sum2 = p[i0] + p[i1];
        float w0 = p[i0] / sum2, w1 = p[i1] / sum2;
        int s0 = atomicAdd(&g_counts[i0], 1);
        g_tok[i0 * Bn + s0] = b;
        g_pos[b * 2 + 0] = i0 * Bn + s0;
        g_wk[b * 2 + 0] = w0;
        int s1 = atomicAdd(&g_counts[i1], 1);
        g_tok[i1 * Bn + s1] = b;
        g_pos[b * 2 + 1] = i1 * Bn + s1;
        g_wk[b * 2 + 1] = w1;
    }
}

// ---------------- bf16x3 compute via ldmatrix.x4 (proven; gemm1) ----------------
template <int MT, int AP>
__device__ __forceinline__ void compute_tile(uint32_t sbuf, int lane, int warp_m, int warp_n,
                                             float acc[MT][4][4]) {
    uint32_t Ahi = sbuf, Alo = sbuf + AP;
    uint32_t Bhi = sbuf + 2 * AP, Blo = Bhi + PLANE_Bp;
    int rsel = lane & 7, grp = lane >> 3;
#pragma unroll
    for (int ks = 0; ks < 2; ks++) {
        uint32_t bh[4][2], bl[4][2];
#pragma unroll
        for (int p = 0; p < 2; p++) {
            int nt = 2 * p + (grp >> 1);
            int n = warp_n * 32 + nt * 8 + rsel;
            int cB = 2 * ks + (grp & 1);
            uint32_t off = (uint32_t)n * 64 + (uint32_t)((cB ^ SWZ_R(n)) << 4);
            ldsm_x4(bh[2 * p][0], bh[2 * p][1], bh[2 * p + 1][0], bh[2 * p + 1][1], Bhi + off);
            ldsm_x4(bl[2 * p][0], bl[2 * p][1], bl[2 * p + 1][0], bl[2 * p + 1][1], Blo + off);
        }
#pragma unroll
        for (int mt = 0; mt < MT; mt++) {
            int r = warp_m * (MT * 16) + mt * 16 + ((grp & 1) << 3) + rsel;
            int cA = 2 * ks + (grp >> 1);
            uint32_t off = (uint32_t)r * 64 + (uint32_t)((cA ^ SWZ_R(r)) << 4);
            uint32_t ah[4], al[4];
            ldsm_x4(ah[0], ah[1], ah[2], ah[3], Ahi + off);
            ldsm_x4(al[0], al[1], al[2], al[3], Alo + off);
#pragma unroll
            for (int nt = 0; nt < 4; nt++) {
                mma_bf16(acc[mt][nt], ah, bh[nt]);
                mma_bf16(acc[mt][nt], ah, bl[nt]);
                mma_bf16(acc[mt][nt], al, bh[nt]);
            }
        }
    }
}

// ---------------- fp16 single-MMA compute (gemm2): A plane @sbuf, B plane @sbuf+4096 ----------------
__device__ __forceinline__ void compute_tile_f16(uint32_t sbuf, int lane, int warp_m, int warp_n,
                                                 float acc[4][4]) {
    uint32_t Af = sbuf, Bf = sbuf + PLANE_Bp;
    int rsel = lane & 7, grp = lane >> 3;
#pragma unroll
    for (int ks = 0; ks < 2; ks++) {
        uint32_t bf[4][2];
#pragma unroll
        for (int p = 0; p < 2; p++) {
            int nt = 2 * p + (grp >> 1);
            int n = warp_n * 32 + nt * 8 + rsel;
            int cB = 2 * ks + (grp & 1);
            uint32_t off = (uint32_t)n * 64 + (uint32_t)((cB ^ SWZ_R(n)) << 4);
            ldsm_x4(bf[2 * p][0], bf[2 * p][1], bf[2 * p + 1][0], bf[2 * p + 1][1], Bf + off);
        }
        int r = warp_m * 16 + ((grp & 1) << 3) + rsel;
        int cA = 2 * ks + (grp >> 1);
        uint32_t off = (uint32_t)r * 64 + (uint32_t)((cA ^ SWZ_R(r)) << 4);
        uint32_t af[4];
        ldsm_x4(af[0], af[1], af[2], af[3], Af + off);
#pragma unroll
        for (int nt = 0; nt < 4; nt++)
            mma_f16(acc[nt], af, bf[nt]);
    }
}

// ======================= GEMM1: M=128/N=64, split-load pipeline (R14-proven), fp16 h out =======================
__global__ void __launch_bounds__(256, 2) gemm1_mma(const float* __restrict__ x,
                                                    const float* __restrict__ W1,
                                                    const float* __restrict__ b1) {
    extern __shared__ char smem[];
    uint32_t sbase = (uint32_t)__cvta_generic_to_shared(smem);
    int tid = threadIdx.x, wid = tid >> 5, lane = tid & 31;
    int warp_m = wid & 3, warp_n = wid >> 2;

    int e = blockIdx.z;
    int count = g_counts[e];
    int m0 = blockIdx.y * 128;
    if (m0 >= count) return;
    int n0 = blockIdx.x * 64;

    const float* W1e = W1 + (size_t)e * In * Hn;
    const int* tokp = g_tok + e * Bn;

    float acc[2][4][4];
#pragma unroll
    for (int i = 0; i < 2; i++)
#pragma unroll
        for (int j = 0; j < 4; j++)
#pragma unroll
            for (int k = 0; k < 4; k++) acc[i][j][k] = 0.f;

    int arow0 = tid >> 2, ach = tid & 3;
    int gr0 = m0 + arow0, gr1 = m0 + arow0 + 64;
    int tok0 = tokp[gr0 < count ? gr0 : count - 1];
    int tok1 = tokp[gr1 < count ? gr1 : count - 1];
    const float* Asrc0 = x + (size_t)tok0 * In + ach * 8;
    const float* Asrc1 = x + (size_t)tok1 * In + ach * 8;
    uint32_t adst0 = (uint32_t)arow0 * 64 + (uint32_t)((ach ^ SWZ_R(arow0)) * 16);
    uint32_t adst1 = (uint32_t)(arow0 + 64) * 64 + (uint32_t)((ach ^ SWZ_R(arow0 + 64)) * 16);
    int bn = tid & 63, bkg = tid >> 6;
    uint32_t bdst = (uint32_t)bn * 64 + (uint32_t)((bkg ^ SWZ_R(bn)) * 16);

    float fA[16], fB[8];

    auto ld = [&](int kt) {
        float4 v0 = *reinterpret_cast<const float4*>(Asrc0 + kt);
        float4 v1 = *reinterpret_cast<const float4*>(Asrc0 + kt + 4);
        fA[0] = v0.x; fA[1] = v0.y; fA[2] = v0.z; fA[3] = v0.w;
        fA[4] = v1.x; fA[5] = v1.y; fA[6] = v1.z; fA[7] = v1.w;
        float4 v2 = *reinterpret_cast<const float4*>(Asrc1 + kt);
        float4 v3 = *reinterpret_cast<const float4*>(Asrc1 + kt + 4);
        fA[8] = v2.x; fA[9] = v2.y; fA[10] = v2.z; fA[11] = v2.w;
        fA[12] = v3.x; fA[13] = v3.y; fA[14] = v3.z; fA[15] = v3.w;
        const float* src = W1e + (size_t)(kt + bkg * 8) * Hn + n0 + bn;
#pragma unroll
        for (int j = 0; j < 8; j++) fB[j] = src[(size_t)j * Hn];
    };
    auto st = [&](int b) {
        char* base = smem + b * BUF1_B;
        uint32_t hi[4], lo[4];
#pragma unroll
        for (int half = 0; half < 2; half++) {
#pragma unroll
            for (int j = 0; j < 4; j++) {
                __nv_bfloat16 h0, l0, h1, l1;
                split_bf16(fA[half * 8 + 2 * j], h0, l0);
                split_bf16(fA[half * 8 + 2 * j + 1], h1, l1);
                hi[j] = pack2(h0, h1); lo[j] = pack2(l0, l1);
            }
            uint32_t ad = half ? adst1 : adst0;
            *reinterpret_cast<uint4*>(base + ad)            = make_uint4(hi[0], hi[1], hi[2], hi[3]);
            *reinterpret_cast<uint4*>(base + PLANE_A1 + ad) = make_uint4(lo[0], lo[1], lo[2], lo[3]);
        }
#pragma unroll
        for (int j = 0; j < 4; j++) {
            __nv_bfloat16 h0, l0, h1, l1;
            split_bf16(fB[2 * j], h0, l0);
            split_bf16(fB[2 * j + 1], h1, l1);
            hi[j] = pack2(h0, h1); lo[j] = pack2(l0, l1);
        }
        *reinterpret_cast<uint4*>(base + 2 * PLANE_A1 + bdst)            = make_uint4(hi[0], hi[1], hi[2], hi[3]);
        *reinterpret_cast<uint4*>(base + 2 * PLANE_A1 + PLANE_Bp + bdst) = make_uint4(lo[0], lo[1], lo[2], lo[3]);
    };

    const int NC = In / 32;    // 16
    ld(0); st(0);
    __syncthreads();
    for (int c = 0; c < NC; c++) {
        bool pre = (c + 1 < NC);
        if (pre) ld((c + 1) * 32);
        compute_tile<2, PLANE_A1>(sbase + (uint32_t)((c & 1) * BUF1_B), lane, warp_m, warp_n, acc);
        if (pre) st((c + 1) & 1);
        __syncthreads();
    }

    // epilogue: +bias, ReLU -> fp16 h plane
#pragma unroll
    for (int mt = 0; mt < 2; mt++) {
        int row_l = warp_m * 32 + mt * 16 + (lane >> 2);
#pragma unroll
        for (int nt = 0; nt < 4; nt++) {
            int ncol_l = warp_n * 32 + nt * 8 + (lane & 3) * 2;
            float bb0 = b1[e * Hn + n0 + ncol_l];
            float bb1 = b1[e * Hn + n0 + ncol_l + 1];
#pragma unroll
            for (int h = 0; h < 2; h++) {
                int grow = m0 + row_l + h * 8;
                float v0 = fmaxf(acc[mt][nt][h * 2 + 0] + bb0, 0.f);
                float v1 = fmaxf(acc[mt][nt][h * 2 + 1] + bb1, 0.f);
                size_t off = (size_t)(e * Bn + grow) * Hn + n0 + ncol_l;
                *reinterpret_cast<uint32_t*>(g_hf16 + off) = pack2h(v0, v1);
            }
        }
    }
}

// ======================= GEMM2: fp16 single-MMA, K-split-2, 3-stage cp.async pipeline =======================
__global__ void __launch_bounds__(256, 4) gemm2_mma(const float* __restrict__ W2) {
    extern __shared__ char smem[];
    uint32_t sbase = (uint32_t)__cvta_generic_to_shared(smem);
    int tid = threadIdx.x, wid = tid >> 5, lane = tid & 31;
    int warp_m = wid & 3, warp_n = wid >> 2;

    int e = blockIdx.z;
    int count = g_counts[e];
    int kh = blockIdx.y & 1;
    int m0 = (blockIdx.y >> 1) * 64;
    if (m0 >= count) return;
    int n0 = blockIdx.x * 64;
    int kbase = kh * (Hn / 2);

    const __half* Ag = g_hf16 + (size_t)(e * Bn + m0) * Hn + kbase;
    const float* W2e = W2 + (size_t)e * Hn * On + (size_t)kbase * On;
    float* yout = (kh ? g_y2 : g_y);

    float acc[4][4];
#pragma unroll
    for (int j = 0; j < 4; j++)
#pragma unroll
        for (int k = 0; k < 4; k++) acc[j][k] = 0.f;

    int arow = tid >> 2, ach = tid & 3;
    uint32_t adst = (uint32_t)arow * 64 + (uint32_t)((ach ^ SWZ_R(arow)) * 16);
    int bn = tid & 63, bkg = tid >> 6;
    uint32_t bdst = (uint32_t)bn * 64 + (uint32_t)((bkg ^ SWZ_R(bn)) * 16);

    float fB[8];

    auto aload = [&](int b, int kt) {
        size_t src = (size_t)arow * Hn + kt + ach * 8;
        CP16(sbase + (uint32_t)(b * BUF2_B) + adst, Ag + src);
    };
    auto bload = [&](int kt) {
        const float* src = W2e + (size_t)(kt + bkg * 8) * On + n0 + bn;
#pragma unroll
        for (int j = 0; j < 8; j++) fB[j] = src[(size_t)j * On];
    };
    auto bstore = [&](int b) {
        uint32_t hv[4];
#pragma unroll
        for (int j = 0; j < 4; j++) hv[j] = pack2h(fB[2 * j], fB[2 * j + 1]);
        char* base = smem + b * BUF2_B + PLANE_Bp;
        *reinterpret_cast<uint4*>(base + bdst) = make_uint4(hv[0], hv[1], hv[2], hv[3]);
    };

    const int NC = (Hn / 2) / 32;    // 32

    bload(0);  aload(0, 0);  CPCOMMIT(); bstore(0);
    bload(32); aload(1, 32); CPCOMMIT(); bstore(1);

    for (int c = 0; c < NC; c++) {
        if (c + 1 < NC) { CPWAIT1(); } else { CPWAIT0(); }
        __syncthreads();
        bool pre = (c + 2 < NC);
        if (pre) {
            int kt2 = (c + 2) * 32;
            bload(kt2);
            aload((c + 2) % 3, kt2);
            CPCOMMIT();
        }
        compute_tile_f16(sbase + (uint32_t)((c % 3) * BUF2_B), lane, warp_m, warp_n, acc);
        if (pre) bstore((c + 2) % 3);
    }

#pragma unroll
    for (int nt = 0; nt < 4; nt++) {
        int ncol_l = warp_n * 32 + nt * 8 + (lane & 3) * 2;
#pragma unroll
        for (int h = 0; h < 2; h++) {
            int grow = m0 + warp_m * 16 + (lane >> 2) + h * 8;
            float2 v = make_float2(acc[nt][h * 2 + 0], acc[nt][h * 2 + 1]);
            *reinterpret_cast<float2*>(yout + (size_t)(e * Bn + grow) * On + n0 + ncol_l) = v;
        }
    }
}

// ---------------- combine (+ b2), sums the two K-halves (proven) ----------------
__global__ void combine_kernel(const float* __restrict__ b2, float* __restrict__ out) {
    int idx = blockIdx.x * 256 + threadIdx.x;
    int b = idx >> 7;
    int o = (idx & 127) * 4;
    int p0 = g_pos[b * 2 + 0], p1 = g_pos[b * 2 + 1];
    float w0 = g_wk[b * 2 + 0], w1 = g_wk[b * 2 + 1];
    int e0 = p0 >> 10, e1 = p1 >> 10;
    float4 ya0 = *reinterpret_cast<const float4*>(g_y  + (size_t)p0 * On + o);
    float4 yb0 = *reinterpret_cast<const float4*>(g_y2 + (size_t)p0 * On + o);
    float4 ya1 = *reinterpret_cast<const float4*>(g_y  + (size_t)p1 * On + o);
    float4 yb1 = *reinterpret_cast<const float4*>(g_y2 + (size_t)p1 * On + o);
    float4 c0 = *reinterpret_cast<const float4*>(b2 + (size_t)e0 * On + o);
    float4 c1 = *reinterpret_cast<const float4*>(b2 + (size_t)e1 * On + o);
    float4 r;
    r.x = w0 * (ya0.x + yb0.x + c0.x) + w1 * (ya1.x + yb1.x + c1.x);
    r.y = w0 * (ya0.y + yb0.y + c0.y) + w1 * (ya1.y + yb1.y + c1.y);
    r.z = w0 * (ya0.z + yb0.z + c0.z) + w1 * (ya1.z + yb1.z + c1.z);
    r.w = w0 * (ya0.w + yb0.w + c0.w) + w1 * (ya1.w + yb1.w + c1.w);
    *reinterpret_cast<float4*>(out + (size_t)b * On + o) = r;
}

// ---------------- launch ----------------
extern "C" void kernel_launch(void* const* d_in, const int* in_sizes, int n_in,
                              void* d_out, int out_size) {
    const float* x  = (const float*)d_in[0];
    const float* Wg = (const float*)d_in[1];
    const float* bg = (const float*)d_in[2];
    const float* W1 = (const float*)d_in[3];
    const float* b1 = (const float*)d_in[4];
    const float* W2 = (const float*)d_in[5];
    const float* b2 = (const float*)d_in[6];
    float* out = (float*)d_out;

    zero_counts_kernel<<<1, 32>>>();
    gate_kernel<<<Bn / 8, 256>>>(x, Wg, bg);
    gemm1_mma<<<dim3(Hn / 64, Bn / 128, En), 256, GSMEM1>>>(x, W1, b1);
    gemm2_mma<<<dim3(On / 64, (Bn / 64) * 2, En), 256, GSMEM2>>>(W2);
    combine_kernel<<<(Bn * On / 4) / 256, 256>>>(b2, out);
}

// round 16
// speedup vs baseline: 1.8050x; 1.2466x over previous
#include <cuda_runtime.h>
#include <cuda_bf16.h>
#include <cuda_fp16.h>
#include <math.h>
#include <stdint.h>

#define Bn 1024
#define In 512
#define Hn 2048
#define On 512
#define En 8

// ---------------- scratch (device globals; zero-init, 16B aligned; ~64MB) ----------------
__device__ __align__(16) int   g_counts[En];
__device__ __align__(16) int   g_tok[En * Bn];
__device__ __align__(16) int   g_pos[Bn * 2];
__device__ __align__(16) float g_wk[Bn * 2];
__device__ __align__(16) __half g_hf16[En * Bn * Hn];        // 32 MB (fp16 hidden)
__device__ __align__(16) float g_y[En * Bn * On];            // 16 MB (K-half 0)
__device__ __align__(16) float g_y2[En * Bn * On];           // 16 MB (K-half 1)

// ---------------- mma / ldmatrix / cp.async helpers ----------------
__device__ __forceinline__ void mma_f16(float* c, const uint32_t* a, const uint32_t* b) {
    asm volatile(
        "mma.sync.aligned.m16n8k16.row.col.f32.f16.f16.f32 "
        "{%0,%1,%2,%3}, {%4,%5,%6,%7}, {%8,%9}, {%0,%1,%2,%3};"
        : "+f"(c[0]), "+f"(c[1]), "+f"(c[2]), "+f"(c[3])
        : "r"(a[0]), "r"(a[1]), "r"(a[2]), "r"(a[3]), "r"(b[0]), "r"(b[1]));
}
__device__ __forceinline__ void ldsm_x4(uint32_t& r0, uint32_t& r1, uint32_t& r2, uint32_t& r3,
                                        uint32_t addr) {
    asm volatile("ldmatrix.sync.aligned.m8n8.x4.shared.b16 {%0,%1,%2,%3}, [%4];"
        : "=r"(r0), "=r"(r1), "=r"(r2), "=r"(r3) : "r"(addr));
}
#define CP16(dst, src) asm volatile("cp.async.cg.shared.global [%0], [%1], 16;" :: "r"(dst), "l"(src))
#define CPCOMMIT()     asm volatile("cp.async.commit_group;" ::: "memory")
#define CPWAIT1()      asm volatile("cp.async.wait_group 1;" ::: "memory")
#define CPWAIT0()      asm volatile("cp.async.wait_group 0;" ::: "memory")

__device__ __forceinline__ uint32_t pack2h(float a, float b) {
    __half2 v = __floats2half2_rn(a, b);
    return *reinterpret_cast<uint32_t*>(&v);
}

// ---------------- pad-free swizzled smem planes (proven R9-R15) ----------------
// plane: rows x 32 k fp16 = 64 B/row = 4 chunks of 16 B. phys(r,c) = r*64 + ((c ^ ((r>>1)&3))*16)
#define PLANE_Bp 4096                 // 64 rows
#define SWZ_R(r) (((r) >> 1) & 3)

#define PLANE_A1 8192                 // gemm1 A: 128 rows fp16
#define BUF1_B   (PLANE_A1 + PLANE_Bp)    // 12288
#define GSMEM1   (2 * BUF1_B)             // 24576 double buffer

#define BUF2_B   (2 * PLANE_Bp)       // gemm2: A_f16 + B_f16 = 8192
#define GSMEM2   (3 * BUF2_B)         // 24576 triple buffer

// ---------------- kernel 0: zero counters ----------------
__global__ void zero_counts_kernel() {
    if (threadIdx.x < En) g_counts[threadIdx.x] = 0;
}

// ---------------- kernel 1: gating (proven) ----------------
__global__ void gate_kernel(const float* __restrict__ x,
                            const float* __restrict__ Wg,
                            const float* __restrict__ bg) {
    int warp = threadIdx.x >> 5, lane = threadIdx.x & 31;
    int b = blockIdx.x * 8 + warp;
    const float* xr = x + (size_t)b * In;

    float acc[En];
#pragma unroll
    for (int e = 0; e < En; e++) acc[e] = 0.f;
    for (int i = lane; i < In; i += 32) {
        float xv = xr[i];
        const float4* w4 = reinterpret_cast<const float4*>(Wg + (size_t)i * En);
        float4 w0 = w4[0], w1 = w4[1];
        acc[0] += xv * w0.x; acc[1] += xv * w0.y;
        acc[2] += xv * w0.z; acc[3] += xv * w0.w;
        acc[4] += xv * w1.x; acc[5] += xv * w1.y;
        acc[6] += xv * w1.z; acc[7] += xv * w1.w;
    }
#pragma unroll
    for (int e = 0; e < En; e++) {
#pragma unroll
        for (int off = 16; off; off >>= 1)
            acc[e] += __shfl_xor_sync(0xffffffffu, acc[e], off);
    }
    if (lane == 0) {
        float lg[En]; float m = -1e30f;
#pragma unroll
        for (int e = 0; e < En; e++) { lg[e] = acc[e] + bg[e]; m = fmaxf(m, lg[e]); }
        float p[En]; float s = 0.f;
#pragma unroll
        for (int e = 0; e < En; e++) { p[e] = expf(lg[e] - m); s += p[e]; }
#pragma unroll
        for (int e = 0; e < En; e++) p[e] /= s;
        int i0 = 0;
#pragma unroll
        for (int e = 1; e < En; e++) if (p[e] > p[i0]) i0 = e;
        int i1 = (i0 == 0) ? 1 : 0;
#pragma unroll
        for (int e = 0; e < En; e++) if (e != i0 && p[e] > p[i1]) i1 = e;
        float sum2 = p[i0] + p[i1];
        float w0 = p[i0] / sum2, w1 = p[i1] / sum2;
        int s0 = atomicAdd(&g_counts[i0], 1);
        g_tok[i0 * Bn + s0] = b;
        g_pos[b * 2 + 0] = i0 * Bn + s0;
        g_wk[b * 2 + 0] = w0;
        int s1 = atomicAdd(&g_counts[i1], 1);
        g_tok[i1 * Bn + s1] = b;
        g_pos[b * 2 + 1] = i1 * Bn + s1;
        g_wk[b * 2 + 1] = w1;
    }
}

// ---------------- fp16 single-MMA compute (proven R15): A plane @sbuf, B plane @sbuf+AP ----------------
template <int MT, int AP>
__device__ __forceinline__ void compute_tile_f16(uint32_t sbuf, int lane, int warp_m, int warp_n,
                                                 float acc[MT][4][4]) {
    uint32_t Af = sbuf, Bf = sbuf + AP;
    int rsel = lane & 7, grp = lane >> 3;
#pragma unroll
    for (int ks = 0; ks < 2; ks++) {
        uint32_t bf[4][2];
#pragma unroll
        for (int p = 0; p < 2; p++) {
            int nt = 2 * p + (grp >> 1);
            int n = warp_n * 32 + nt * 8 + rsel;
            int cB = 2 * ks + (grp & 1);
            uint32_t off = (uint32_t)n * 64 + (uint32_t)((cB ^ SWZ_R(n)) << 4);
            ldsm_x4(bf[2 * p][0], bf[2 * p][1], bf[2 * p + 1][0], bf[2 * p + 1][1], Bf + off);
        }
#pragma unroll
        for (int mt = 0; mt < MT; mt++) {
            int r = warp_m * (MT * 16) + mt * 16 + ((grp & 1) << 3) + rsel;
            int cA = 2 * ks + (grp >> 1);
            uint32_t off = (uint32_t)r * 64 + (uint32_t)((cA ^ SWZ_R(r)) << 4);
            uint32_t af[4];
            ldsm_x4(af[0], af[1], af[2], af[3], Af + off);
#pragma unroll
            for (int nt = 0; nt < 4; nt++)
                mma_f16(acc[mt][nt], af, bf[nt]);
        }
    }
}

// ======================= GEMM1: fp16, M=128/N=64, split-load double-buffer pipeline =======================
__global__ void __launch_bounds__(256, 2) gemm1_mma(const float* __restrict__ x,
                                                    const float* __restrict__ W1,
                                                    const float* __restrict__ b1) {
    extern __shared__ char smem[];
    uint32_t sbase = (uint32_t)__cvta_generic_to_shared(smem);
    int tid = threadIdx.x, wid = tid >> 5, lane = tid & 31;
    int warp_m = wid & 3, warp_n = wid >> 2;

    int e = blockIdx.z;
    int count = g_counts[e];
    int m0 = blockIdx.y * 128;
    if (m0 >= count) return;
    int n0 = blockIdx.x * 64;

    const float* W1e = W1 + (size_t)e * In * Hn;
    const int* tokp = g_tok + e * Bn;

    float acc[2][4][4];
#pragma unroll
    for (int i = 0; i < 2; i++)
#pragma unroll
        for (int j = 0; j < 4; j++)
#pragma unroll
            for (int k = 0; k < 4; k++) acc[i][j][k] = 0.f;

    // A: two rows per thread (arow0, arow0+64), chunk ach of 8 floats
    int arow0 = tid >> 2, ach = tid & 3;
    int gr0 = m0 + arow0, gr1 = m0 + arow0 + 64;
    int tok0 = tokp[gr0 < count ? gr0 : count - 1];
    int tok1 = tokp[gr1 < count ? gr1 : count - 1];
    const float* Asrc0 = x + (size_t)tok0 * In + ach * 8;
    const float* Asrc1 = x + (size_t)tok1 * In + ach * 8;
    uint32_t adst0 = (uint32_t)arow0 * 64 + (uint32_t)((ach ^ SWZ_R(arow0)) * 16);
    uint32_t adst1 = (uint32_t)(arow0 + 64) * 64 + (uint32_t)((ach ^ SWZ_R(arow0 + 64)) * 16);
    int bn = tid & 63, bkg = tid >> 6;
    uint32_t bdst = (uint32_t)bn * 64 + (uint32_t)((bkg ^ SWZ_R(bn)) * 16);

    float fA[16], fB[8];

    auto ld = [&](int kt) {
        float4 v0 = *reinterpret_cast<const float4*>(Asrc0 + kt);
        float4 v1 = *reinterpret_cast<const float4*>(Asrc0 + kt + 4);
        fA[0] = v0.x; fA[1] = v0.y; fA[2] = v0.z; fA[3] = v0.w;
        fA[4] = v1.x; fA[5] = v1.y; fA[6] = v1.z; fA[7] = v1.w;
        float4 v2 = *reinterpret_cast<const float4*>(Asrc1 + kt);
        float4 v3 = *reinterpret_cast<const float4*>(Asrc1 + kt + 4);
        fA[8] = v2.x; fA[9] = v2.y; fA[10] = v2.z; fA[11] = v2.w;
        fA[12] = v3.x; fA[13] = v3.y; fA[14] = v3.z; fA[15] = v3.w;
        const float* src = W1e + (size_t)(kt + bkg * 8) * Hn + n0 + bn;
#pragma unroll
        for (int j = 0; j < 8; j++) fB[j] = src[(size_t)j * Hn];
    };
    auto st = [&](int b) {
        char* base = smem + b * BUF1_B;
        uint32_t hv[4];
#pragma unroll
        for (int half = 0; half < 2; half++) {
#pragma unroll
            for (int j = 0; j < 4; j++)
                hv[j] = pack2h(fA[half * 8 + 2 * j], fA[half * 8 + 2 * j + 1]);
            uint32_t ad = half ? adst1 : adst0;
            *reinterpret_cast<uint4*>(base + ad) = make_uint4(hv[0], hv[1], hv[2], hv[3]);
        }
#pragma unroll
        for (int j = 0; j < 4; j++)
            hv[j] = pack2h(fB[2 * j], fB[2 * j + 1]);
        *reinterpret_cast<uint4*>(base + PLANE_A1 + bdst) = make_uint4(hv[0], hv[1], hv[2], hv[3]);
    };

    const int NC = In / 32;    // 16
    ld(0); st(0);
    __syncthreads();
    for (int c = 0; c < NC; c++) {
        bool pre = (c + 1 < NC);
        if (pre) ld((c + 1) * 32);
        compute_tile_f16<2, PLANE_A1>(sbase + (uint32_t)((c & 1) * BUF1_B), lane, warp_m, warp_n, acc);
        if (pre) st((c + 1) & 1);
        __syncthreads();
    }

    // epilogue: +bias, ReLU -> fp16 h plane
#pragma unroll
    for (int mt = 0; mt < 2; mt++) {
        int row_l = warp_m * 32 + mt * 16 + (lane >> 2);
#pragma unroll
        for (int nt = 0; nt < 4; nt++) {
            int ncol_l = warp_n * 32 + nt * 8 + (lane & 3) * 2;
            float bb0 = b1[e * Hn + n0 + ncol_l];
            float bb1 = b1[e * Hn + n0 + ncol_l + 1];
#pragma unroll
            for (int h = 0; h < 2; h++) {
                int grow = m0 + row_l + h * 8;
                float v0 = fmaxf(acc[mt][nt][h * 2 + 0] + bb0, 0.f);
                float v1 = fmaxf(acc[mt][nt][h * 2 + 1] + bb1, 0.f);
                size_t off = (size_t)(e * Bn + grow) * Hn + n0 + ncol_l;
                *reinterpret_cast<uint32_t*>(g_hf16 + off) = pack2h(v0, v1);
            }
        }
    }
}

// ======================= GEMM2 (byte-identical to R15, proven): fp16, K-split-2, 3-stage cp.async =======================
__global__ void __launch_bounds__(256, 4) gemm2_mma(const float* __restrict__ W2) {
    extern __shared__ char smem[];
    uint32_t sbase = (uint32_t)__cvta_generic_to_shared(smem);
    int tid = threadIdx.x, wid = tid >> 5, lane = tid & 31;
    int warp_m = wid & 3, warp_n = wid >> 2;

    int e = blockIdx.z;
    int count = g_counts[e];
    int kh = blockIdx.y & 1;
    int m0 = (blockIdx.y >> 1) * 64;
    if (m0 >= count) return;
    int n0 = blockIdx.x * 64;
    int kbase = kh * (Hn / 2);

    const __half* Ag = g_hf16 + (size_t)(e * Bn + m0) * Hn + kbase;
    const float* W2e = W2 + (size_t)e * Hn * On + (size_t)kbase * On;
    float* yout = (kh ? g_y2 : g_y);

    float acc[1][4][4];
#pragma unroll
    for (int j = 0; j < 4; j++)
#pragma unroll
        for (int k = 0; k < 4; k++) acc[0][j][k] = 0.f;

    int arow = tid >> 2, ach = tid & 3;
    uint32_t adst = (uint32_t)arow * 64 + (uint32_t)((ach ^ SWZ_R(arow)) * 16);
    int bn = tid & 63, bkg = tid >> 6;
    uint32_t bdst = (uint32_t)bn * 64 + (uint32_t)((bkg ^ SWZ_R(bn)) * 16);

    float fB[8];

    auto aload = [&](int b, int kt) {
        size_t src = (size_t)arow * Hn + kt + ach * 8;
        CP16(sbase + (uint32_t)(b * BUF2_B) + adst, Ag + src);
    };
    auto bload = [&](int kt) {
        const float* src = W2e + (size_t)(kt + bkg * 8) * On + n0 + bn;
#pragma unroll
        for (int j = 0; j < 8; j++) fB[j] = src[(size_t)j * On];
    };
    auto bstore = [&](int b) {
        uint32_t hv[4];
#pragma unroll
        for (int j = 0; j < 4; j++) hv[j] = pack2h(fB[2 * j], fB[2 * j + 1]);
        char* base = smem + b * BUF2_B + PLANE_Bp;
        *reinterpret_cast<uint4*>(base + bdst) = make_uint4(hv[0], hv[1], hv[2], hv[3]);
    };

    const int NC = (Hn / 2) / 32;    // 32

    bload(0);  aload(0, 0);  CPCOMMIT(); bstore(0);
    bload(32); aload(1, 32); CPCOMMIT(); bstore(1);

    for (int c = 0; c < NC; c++) {
        if (c + 1 < NC) { CPWAIT1(); } else { CPWAIT0(); }
        __syncthreads();
        bool pre = (c + 2 < NC);
        if (pre) {
            int kt2 = (c + 2) * 32;
            bload(kt2);
            aload((c + 2) % 3, kt2);
            CPCOMMIT();
        }
        compute_tile_f16<1, PLANE_Bp>(sbase + (uint32_t)((c % 3) * BUF2_B), lane, warp_m, warp_n, acc);
        if (pre) bstore((c + 2) % 3);
    }

#pragma unroll
    for (int nt = 0; nt < 4; nt++) {
        int ncol_l = warp_n * 32 + nt * 8 + (lane & 3) * 2;
#pragma unroll
        for (int h = 0; h < 2; h++) {
            int grow = m0 + warp_m * 16 + (lane >> 2) + h * 8;
            float2 v = make_float2(acc[0][nt][h * 2 + 0], acc[0][nt][h * 2 + 1]);
            *reinterpret_cast<float2*>(yout + (size_t)(e * Bn + grow) * On + n0 + ncol_l) = v;
        }
    }
}

// ---------------- combine (+ b2), sums the two K-halves (proven) ----------------
__global__ void combine_kernel(const float* __restrict__ b2, float* __restrict__ out) {
    int idx = blockIdx.x * 256 + threadIdx.x;
    int b = idx >> 7;
    int o = (idx & 127) * 4;
    int p0 = g_pos[b * 2 + 0], p1 = g_pos[b * 2 + 1];
    float w0 = g_wk[b * 2 + 0], w1 = g_wk[b * 2 + 1];
    int e0 = p0 >> 10, e1 = p1 >> 10;
    float4 ya0 = *reinterpret_cast<const float4*>(g_y  + (size_t)p0 * On + o);
    float4 yb0 = *reinterpret_cast<const float4*>(g_y2 + (size_t)p0 * On + o);
    float4 ya1 = *reinterpret_cast<const float4*>(g_y  + (size_t)p1 * On + o);
    float4 yb1 = *reinterpret_cast<const float4*>(g_y2 + (size_t)p1 * On + o);
    float4 c0 = *reinterpret_cast<const float4*>(b2 + (size_t)e0 * On + o);
    float4 c1 = *reinterpret_cast<const float4*>(b2 + (size_t)e1 * On + o);
    float4 r;
    r.x = w0 * (ya0.x + yb0.x + c0.x) + w1 * (ya1.x + yb1.x + c1.x);
    r.y = w0 * (ya0.y + yb0.y + c0.y) + w1 * (ya1.y + yb1.y + c1.y);
    r.z = w0 * (ya0.z + yb0.z + c0.z) + w1 * (ya1.z + yb1.z + c1.z);
    r.w = w0 * (ya0.w + yb0.w + c0.w) + w1 * (ya1.w + yb1.w + c1.w);
    *reinterpret_cast<float4*>(out + (size_t)b * On + o) = r;
}

// ---------------- launch ----------------
extern "C" void kernel_launch(void* const* d_in, const int* in_sizes, int n_in,
                              void* d_out, int out_size) {
    const float* x  = (const float*)d_in[0];
    const float* Wg = (const float*)d_in[1];
    const float* bg = (const float*)d_in[2];
    const float* W1 = (const float*)d_in[3];
    const float* b1 = (const float*)d_in[4];
    const float* W2 = (const float*)d_in[5];
    const float* b2 = (const float*)d_in[6];
    float* out = (float*)d_out;

    zero_counts_kernel<<<1, 32>>>();
    gate_kernel<<<Bn / 8, 256>>>(x, Wg, bg);
    gemm1_mma<<<dim3(Hn / 64, Bn / 128, En), 256, GSMEM1>>>(x, W1, b1);
    gemm2_mma<<<dim3(On / 64, (Bn / 64) * 2, En), 256, GSMEM2>>>(W2);
    combine_kernel<<<(Bn * On / 4) / 256, 256>>>(b2, out);
}